// round 1
// baseline (speedup 1.0000x reference)
#include <cuda_runtime.h>
#include <math.h>

// Problem constants
#define BB 4
#define LL 1024
#define DD 512
#define NN 16
#define OUTD 512
#define NLAYER 2
#define NCH 16          // number of scan chunks
#define LCH 64          // steps per chunk (LL/NCH)

#define BLD (BB*LL*DD)          // 2,097,152
#define BLN (BB*LL*NN)          // 65,536
#define CHN (BB*NCH*DD*NN)      // 524,288

// Scratch (static device globals; no runtime allocation allowed)
__device__ float g_y[BLD];      // layer activation (after linear)
__device__ float g_dt[BLD];     // softplus(dt)
__device__ float g_z[BLD];      // relu(ssm out) before Wlin
__device__ float g_Bm[BLN];
__device__ float g_Cm[BLN];
__device__ float g_P[CHN];      // per-chunk cumulative a-product
__device__ float g_He[CHN];     // per-chunk local end state
__device__ float g_carry[CHN];  // per-chunk initial state

__device__ __forceinline__ float softplusf(float x) {
    return fmaxf(x, 0.f) + log1pf(__expf(-fabsf(x)));
}

// ---------------------------------------------------------------------------
// Tiled fp32 GEMM: C[M,N] = X[M,K] @ W[K,N] + bias, optional softplus.
// BM=128, BN=64, BK=16, 256 threads, thread tile 8x4.
// grid = (N/64, M/128)
// ---------------------------------------------------------------------------
template<int EPI>   // 0: bias only, 1: bias + softplus
__global__ void gemm_k(const float* __restrict__ X, const float* __restrict__ W,
                       const float* __restrict__ bias, float* __restrict__ C,
                       int N, int K)
{
    const int BM = 128, BN = 64, BK = 16;
    __shared__ float As[BK][BM];
    __shared__ float Bs[BK][BN];

    int tid = threadIdx.x;
    int bm = blockIdx.y * BM;
    int bn = blockIdx.x * BN;
    int tx = tid & 15;       // n dir (0..15)
    int ty = tid >> 4;       // m dir (0..15)

    float acc[8][4];
    #pragma unroll
    for (int i = 0; i < 8; i++)
        #pragma unroll
        for (int j = 0; j < 4; j++) acc[i][j] = 0.f;

    int arow = tid >> 2;            // 0..63
    int acol = (tid & 3) << 2;      // 0,4,8,12
    int brow = tid >> 4;            // 0..15
    int bcol = (tid & 15) << 2;     // 0..60

    for (int k0 = 0; k0 < K; k0 += BK) {
        #pragma unroll
        for (int r = 0; r < 2; r++) {
            int m = arow + r * 64;
            float4 v = *(const float4*)(X + (size_t)(bm + m) * K + k0 + acol);
            As[acol + 0][m] = v.x;
            As[acol + 1][m] = v.y;
            As[acol + 2][m] = v.z;
            As[acol + 3][m] = v.w;
        }
        *(float4*)&Bs[brow][bcol] =
            *(const float4*)(W + (size_t)(k0 + brow) * N + bn + bcol);
        __syncthreads();

        #pragma unroll
        for (int kk = 0; kk < BK; kk++) {
            float a[8], bf[4];
            *(float4*)(a)     = *(const float4*)&As[kk][ty * 8];
            *(float4*)(a + 4) = *(const float4*)&As[kk][ty * 8 + 4];
            *(float4*)(bf)    = *(const float4*)&Bs[kk][tx * 4];
            #pragma unroll
            for (int i = 0; i < 8; i++)
                #pragma unroll
                for (int j = 0; j < 4; j++)
                    acc[i][j] = fmaf(a[i], bf[j], acc[i][j]);
        }
        __syncthreads();
    }

    float bv[4];
    *(float4*)bv = *(const float4*)(bias + bn + tx * 4);
    #pragma unroll
    for (int i = 0; i < 8; i++) {
        float4 o;
        float* op = &o.x;
        #pragma unroll
        for (int j = 0; j < 4; j++) {
            float v = acc[i][j] + bv[j];
            if (EPI == 1) v = softplusf(v);
            op[j] = v;
        }
        *(float4*)(C + (size_t)(bm + ty * 8 + i) * N + bn + tx * 4) = o;
    }
}

// ---------------------------------------------------------------------------
// B/C projection: Bm = X@WB + bB, Cm = X@WC + bC   (Nout=16 each)
// One warp per row; lanes 0..15 -> B, lanes 16..31 -> C.
// grid = (B*L)/8, block 256 (8 warps)
// ---------------------------------------------------------------------------
__global__ void gemm_bc_k(const float* __restrict__ X,
                          const float* __restrict__ WB, const float* __restrict__ WC,
                          const float* __restrict__ bB, const float* __restrict__ bC)
{
    int warp = threadIdx.x >> 5, lane = threadIdx.x & 31;
    int row = blockIdx.x * 8 + warp;
    const float* Wp = (lane < NN) ? (WB + lane) : (WC + (lane - NN));
    const float* xr = X + (size_t)row * DD;
    float acc = 0.f;
    #pragma unroll 4
    for (int k = 0; k < DD; k += 4) {
        float4 xv = *(const float4*)(xr + k);
        acc = fmaf(xv.x, Wp[(k + 0) * NN], acc);
        acc = fmaf(xv.y, Wp[(k + 1) * NN], acc);
        acc = fmaf(xv.z, Wp[(k + 2) * NN], acc);
        acc = fmaf(xv.w, Wp[(k + 3) * NN], acc);
    }
    if (lane < NN) g_Bm[(size_t)row * NN + lane] = acc + bB[lane];
    else           g_Cm[(size_t)row * NN + (lane - NN)] = acc + bC[lane - NN];
}

// ---------------------------------------------------------------------------
// Scan pass 1: per (b, chunk, d), compute local scan from zero init.
// Store cumulative product P[n] and end state He[n].
// grid = (DD/128, NCH, BB), block 128
// ---------------------------------------------------------------------------
__global__ void scan1_k(const float* __restrict__ yin, const float* __restrict__ A)
{
    __shared__ float sB[LCH * NN];
    int d = blockIdx.x * 128 + threadIdx.x;
    int c = blockIdx.y, b = blockIdx.z;
    int t0 = c * LCH;

    const float4* src = (const float4*)(g_Bm + ((size_t)b * LL + t0) * NN);
    #pragma unroll
    for (int i = threadIdx.x; i < LCH * NN / 4; i += 128)
        ((float4*)sB)[i] = src[i];
    __syncthreads();

    float av[NN], h[NN], p[NN];
    #pragma unroll
    for (int q = 0; q < 4; q++)
        *(float4*)(av + q * 4) = *(const float4*)(A + (size_t)d * NN + q * 4);
    #pragma unroll
    for (int n = 0; n < NN; n++) { h[n] = 0.f; p[n] = 1.f; }

    const float* dtp = g_dt + ((size_t)b * LL + t0) * DD + d;
    const float* yp  = yin  + ((size_t)b * LL + t0) * DD + d;

    for (int t = 0; t < LCH; t++) {
        float dv = dtp[(size_t)t * DD];
        float u  = dv * yp[(size_t)t * DD];
        #pragma unroll
        for (int n = 0; n < NN; n++) {
            float e = __expf(dv * av[n]);
            p[n] *= e;
            h[n] = fmaf(e, h[n], u * sB[t * NN + n]);
        }
    }

    size_t o = (((size_t)b * NCH + c) * DD + d) * NN;
    #pragma unroll
    for (int q = 0; q < 4; q++) {
        *(float4*)(g_P  + o + q * 4) = *(float4*)(p + q * 4);
        *(float4*)(g_He + o + q * 4) = *(float4*)(h + q * 4);
    }
}

// ---------------------------------------------------------------------------
// Scan pass 2: sequential combine across chunks (tiny).
// One thread per (b, d, n). grid*block = B*D*N = 32768
// ---------------------------------------------------------------------------
__global__ void scan2_k()
{
    int tid = blockIdx.x * blockDim.x + threadIdx.x;
    int b  = tid / (DD * NN);
    int dn = tid % (DD * NN);
    float hc = 0.f;
    for (int c = 0; c < NCH; c++) {
        size_t idx = ((size_t)(b * NCH + c)) * DD * NN + dn;
        g_carry[idx] = hc;
        hc = fmaf(g_P[idx], hc, g_He[idx]);
    }
}

// ---------------------------------------------------------------------------
// Scan pass 3: recompute scan with correct carry-in; produce
// z = relu( sum_n h*C + Dskip*y ).
// grid = (DD/128, NCH, BB), block 128
// ---------------------------------------------------------------------------
__global__ void scan3_k(const float* __restrict__ yin, const float* __restrict__ A,
                        const float* __restrict__ Dskip)
{
    __shared__ float sB[LCH * NN];
    __shared__ float sC[LCH * NN];
    int d = blockIdx.x * 128 + threadIdx.x;
    int c = blockIdx.y, b = blockIdx.z;
    int t0 = c * LCH;

    {
        const float4* srcB = (const float4*)(g_Bm + ((size_t)b * LL + t0) * NN);
        const float4* srcC = (const float4*)(g_Cm + ((size_t)b * LL + t0) * NN);
        #pragma unroll
        for (int i = threadIdx.x; i < LCH * NN / 4; i += 128) {
            ((float4*)sB)[i] = srcB[i];
            ((float4*)sC)[i] = srcC[i];
        }
    }
    __syncthreads();

    float av[NN], h[NN];
    #pragma unroll
    for (int q = 0; q < 4; q++)
        *(float4*)(av + q * 4) = *(const float4*)(A + (size_t)d * NN + q * 4);
    size_t co = (((size_t)b * NCH + c) * DD + d) * NN;
    #pragma unroll
    for (int q = 0; q < 4; q++)
        *(float4*)(h + q * 4) = *(const float4*)(g_carry + co + q * 4);

    float ds = Dskip[d];
    const float* dtp = g_dt + ((size_t)b * LL + t0) * DD + d;
    const float* yp  = yin  + ((size_t)b * LL + t0) * DD + d;
    float* zp        = g_z  + ((size_t)b * LL + t0) * DD + d;

    for (int t = 0; t < LCH; t++) {
        float dv = dtp[(size_t)t * DD];
        float yv = yp[(size_t)t * DD];
        float u  = dv * yv;
        float acc = 0.f;
        #pragma unroll
        for (int n = 0; n < NN; n++) {
            float e = __expf(dv * av[n]);
            h[n] = fmaf(e, h[n], u * sB[t * NN + n]);
            acc = fmaf(h[n], sC[t * NN + n], acc);
        }
        zp[(size_t)t * DD] = fmaxf(fmaf(ds, yv, acc), 0.f);
    }
}

// ---------------------------------------------------------------------------
// Host launcher
// ---------------------------------------------------------------------------
extern "C" void kernel_launch(void* const* d_in, const int* in_sizes, int n_in,
                              void* d_out, int out_size)
{
    const float* x     = (const float*)d_in[0];
    const float* A     = (const float*)d_in[1];
    const float* Dskip = (const float*)d_in[2];
    const float* WB    = (const float*)d_in[3];
    const float* bB    = (const float*)d_in[4];
    const float* WC    = (const float*)d_in[5];
    const float* bC    = (const float*)d_in[6];
    const float* Wdt   = (const float*)d_in[7];
    const float* bdt   = (const float*)d_in[8];
    const float* Wlin  = (const float*)d_in[9];
    const float* blin  = (const float*)d_in[10];
    const float* Wdec  = (const float*)d_in[11];
    const float* bdec  = (const float*)d_in[12];
    float* out = (float*)d_out;

    float *py, *pdt, *pz;
    cudaGetSymbolAddress((void**)&py,  g_y);
    cudaGetSymbolAddress((void**)&pdt, g_dt);
    cudaGetSymbolAddress((void**)&pz,  g_z);

    dim3 gg(DD / 64, (BB * LL) / 128);     // (8, 32)
    dim3 gs(DD / 128, NCH, BB);            // (4, 16, 4)

    const float* cur = x;
    for (int l = 0; l < NLAYER; l++) {
        gemm_k<1><<<gg, 256>>>(cur, Wdt + (size_t)l * DD * DD, bdt + l * DD, pdt, DD, DD);
        gemm_bc_k<<<(BB * LL) / 8, 256>>>(cur, WB + (size_t)l * DD * NN,
                                          WC + (size_t)l * DD * NN,
                                          bB + l * NN, bC + l * NN);
        scan1_k<<<gs, 128>>>(cur, A + (size_t)l * DD * NN);
        scan2_k<<<(BB * DD * NN) / 256, 256>>>();
        scan3_k<<<gs, 128>>>(cur, A + (size_t)l * DD * NN, Dskip + l * DD);
        gemm_k<0><<<gg, 256>>>(pz, Wlin + (size_t)l * DD * DD, blin + l * DD, py, DD, DD);
        cur = py;
    }
    gemm_k<0><<<gg, 256>>>(cur, Wdec, bdec, out, OUTD, DD);
}

// round 3
// speedup vs baseline: 1.3478x; 1.3478x over previous
#include <cuda_runtime.h>
#include <cuda_bf16.h>
#include <math.h>
#include <cstdint>

// Problem constants
#define BB 4
#define LL 1024
#define DD 512
#define NN 16
#define OUTD 512
#define NLAYER 2
#define NCH 16
#define LCH 64

#define BLD (BB*LL*DD)
#define BLN (BB*LL*NN)
#define CHN (BB*NCH*DD*NN)

#define MM (BB*LL)      // 4096 rows
#define KC 1536         // concatenated K (3x512)

// Scratch
__device__ float g_y[BLD];
__device__ float g_dt[BLD];
__device__ float g_z[BLD];
__device__ float g_Bm[BLN];
__device__ float g_Cm[BLN];
__device__ float g_P[CHN];
__device__ float g_He[CHN];
__device__ float g_carry[CHN];
__device__ __nv_bfloat16 g_Xcat[(size_t)MM * KC];        // [Xh | Xl | Xh]
__device__ __nv_bfloat16 g_Wcat[5 * (size_t)DD * KC];    // per weight: [Wh | Wh | Wl] (transposed [N][K])

__device__ __forceinline__ float softplusf(float x) {
    return fmaxf(x, 0.f) + log1pf(__expf(-fabsf(x)));
}

__device__ __forceinline__ uint32_t smem_u32(const void* p) {
    uint32_t a;
    asm("{ .reg .u64 t; cvta.to.shared.u64 t, %1; cvt.u32.u64 %0, t; }" : "=r"(a) : "l"(p));
    return a;
}

// swizzled offset inside an 8KB tile: r in [0,128), c = 16B chunk in [0,4)
__device__ __forceinline__ uint32_t swz_off(int r, int c) {
    int pos = ((r & 1) << 2) | c;
    pos ^= (r >> 1) & 7;
    return ((uint32_t)(r >> 1) << 7) + ((uint32_t)pos << 4);
}

// ---------------------------------------------------------------------------
// bf16 HMMA GEMM: C[M=4096, N=512] = Xcat[M, KC] @ Wcat[N, KC]^T  (TN layout)
// Tile 128x128, BK=32, 3-stage cp.async, 256 threads (8 warps, 2M x 4N).
// grid = (4, 32)
// ---------------------------------------------------------------------------
#define BKC 32
#define STAGES 3

template<int EPI>   // 0: bias, 1: bias + softplus
__global__ void __launch_bounds__(256)
tc_gemm(const __nv_bfloat16* __restrict__ A, const __nv_bfloat16* __restrict__ Bw,
        const float* __restrict__ bias, float* __restrict__ C)
{
    __shared__ __align__(128) char smem[STAGES * 16384];
    uint32_t sbase = smem_u32(smem);

    int tid = threadIdx.x, wid = tid >> 5, lane = tid & 31;
    int bn = blockIdx.x * 128, bm = blockIdx.y * 128;
    int wm = wid >> 2;          // 0..1 -> m offset wm*64
    int wn = wid & 3;           // 0..3 -> n offset wn*32

    // precompute ldmatrix swizzled offsets (per lane)
    int lrow = ((lane >> 3) & 1) * 8 + (lane & 7);
    int lchk = lane >> 4;
    uint32_t aoff[4][2], boff[2][2];
    #pragma unroll
    for (int mt = 0; mt < 4; mt++)
        #pragma unroll
        for (int ks = 0; ks < 2; ks++)
            aoff[mt][ks] = swz_off(wm * 64 + mt * 16 + lrow, lchk + ks * 2);
    #pragma unroll
    for (int nt = 0; nt < 2; nt++)
        #pragma unroll
        for (int ks = 0; ks < 2; ks++)
            boff[nt][ks] = swz_off(wn * 32 + nt * 16 + lrow, lchk + ks * 2) + 8192;

    // cp.async source/dest (per thread, 2 chunks each for A and B per stage)
    int cid0 = tid, cid1 = tid + 256;
    int r0 = cid0 >> 2, c0 = cid0 & 3;
    int r1 = cid1 >> 2, c1 = cid1 & 3;
    uint32_t dA0 = swz_off(r0, c0), dA1 = swz_off(r1, c1);
    const __nv_bfloat16* gA0 = A + (size_t)(bm + r0) * KC + c0 * 8;
    const __nv_bfloat16* gA1 = A + (size_t)(bm + r1) * KC + c1 * 8;
    const __nv_bfloat16* gB0 = Bw + (size_t)(bn + r0) * KC + c0 * 8;
    const __nv_bfloat16* gB1 = Bw + (size_t)(bn + r1) * KC + c1 * 8;

    float acc[4][4][4];
    #pragma unroll
    for (int i = 0; i < 4; i++)
        #pragma unroll
        for (int j = 0; j < 4; j++)
            #pragma unroll
            for (int q = 0; q < 4; q++) acc[i][j][q] = 0.f;

    const int NKB = KC / BKC;   // 48

    // prologue: load stages 0..STAGES-2
    #pragma unroll
    for (int s = 0; s < STAGES - 1; s++) {
        uint32_t st = sbase + s * 16384;
        int ko = s * BKC;
        asm volatile("cp.async.cg.shared.global [%0], [%1], 16;" :: "r"(st + dA0), "l"(gA0 + ko));
        asm volatile("cp.async.cg.shared.global [%0], [%1], 16;" :: "r"(st + dA1), "l"(gA1 + ko));
        asm volatile("cp.async.cg.shared.global [%0], [%1], 16;" :: "r"(st + 8192 + dA0), "l"(gB0 + ko));
        asm volatile("cp.async.cg.shared.global [%0], [%1], 16;" :: "r"(st + 8192 + dA1), "l"(gB1 + ko));
        asm volatile("cp.async.commit_group;" ::: "memory");
    }

    int sbuf = 0;
    for (int kb = 0; kb < NKB; kb++) {
        asm volatile("cp.async.wait_group %0;" :: "n"(STAGES - 2) : "memory");
        __syncthreads();

        int knext = kb + STAGES - 1;
        if (knext < NKB) {
            int sn = knext % STAGES;
            uint32_t st = sbase + sn * 16384;
            int ko = knext * BKC;
            asm volatile("cp.async.cg.shared.global [%0], [%1], 16;" :: "r"(st + dA0), "l"(gA0 + ko));
            asm volatile("cp.async.cg.shared.global [%0], [%1], 16;" :: "r"(st + dA1), "l"(gA1 + ko));
            asm volatile("cp.async.cg.shared.global [%0], [%1], 16;" :: "r"(st + 8192 + dA0), "l"(gB0 + ko));
            asm volatile("cp.async.cg.shared.global [%0], [%1], 16;" :: "r"(st + 8192 + dA1), "l"(gB1 + ko));
        }
        asm volatile("cp.async.commit_group;" ::: "memory");

        uint32_t st = sbase + sbuf * 16384;
        #pragma unroll
        for (int ks = 0; ks < 2; ks++) {
            uint32_t af[4][4], bf[2][4];
            #pragma unroll
            for (int mt = 0; mt < 4; mt++)
                asm volatile("ldmatrix.sync.aligned.m8n8.x4.shared.b16 {%0,%1,%2,%3}, [%4];"
                             : "=r"(af[mt][0]), "=r"(af[mt][1]), "=r"(af[mt][2]), "=r"(af[mt][3])
                             : "r"(st + aoff[mt][ks]));
            #pragma unroll
            for (int nt = 0; nt < 2; nt++)
                asm volatile("ldmatrix.sync.aligned.m8n8.x4.shared.b16 {%0,%1,%2,%3}, [%4];"
                             : "=r"(bf[nt][0]), "=r"(bf[nt][1]), "=r"(bf[nt][2]), "=r"(bf[nt][3])
                             : "r"(st + boff[nt][ks]));
            #pragma unroll
            for (int mt = 0; mt < 4; mt++)
                #pragma unroll
                for (int nf = 0; nf < 4; nf++) {
                    int nt2 = nf >> 1, lo = nf & 1;
                    asm volatile(
                        "mma.sync.aligned.m16n8k16.row.col.f32.bf16.bf16.f32 "
                        "{%0,%1,%2,%3}, {%4,%5,%6,%7}, {%8,%9}, {%0,%1,%2,%3};"
                        : "+f"(acc[mt][nf][0]), "+f"(acc[mt][nf][1]),
                          "+f"(acc[mt][nf][2]), "+f"(acc[mt][nf][3])
                        : "r"(af[mt][0]), "r"(af[mt][1]), "r"(af[mt][2]), "r"(af[mt][3]),
                          "r"(bf[nt2][lo]), "r"(bf[nt2][2 + lo]));
                }
        }
        sbuf++;
        if (sbuf == STAGES) sbuf = 0;
    }

    // epilogue
    int mrow = bm + wm * 64 + (lane >> 2);
    int ncol = bn + wn * 32 + (lane & 3) * 2;
    #pragma unroll
    for (int mt = 0; mt < 4; mt++) {
        #pragma unroll
        for (int nf = 0; nf < 4; nf++) {
            int col = ncol + nf * 8;
            float b0 = bias[col], b1 = bias[col + 1];
            float v0 = acc[mt][nf][0] + b0, v1 = acc[mt][nf][1] + b1;
            float v2 = acc[mt][nf][2] + b0, v3 = acc[mt][nf][3] + b1;
            if (EPI == 1) { v0 = softplusf(v0); v1 = softplusf(v1); v2 = softplusf(v2); v3 = softplusf(v3); }
            int m0 = mrow + mt * 16;
            *(float2*)(C + (size_t)m0 * DD + col)       = make_float2(v0, v1);
            *(float2*)(C + (size_t)(m0 + 8) * DD + col) = make_float2(v2, v3);
        }
    }
}

// ---------------------------------------------------------------------------
// Activation split: X float [4096][512] -> Xcat bf16 [4096][1536] = [hi|lo|hi]
// grid = BLD/4/256, block 256
// ---------------------------------------------------------------------------
__global__ void splitx_k(const float4* __restrict__ in)
{
    int i = blockIdx.x * blockDim.x + threadIdx.x;   // one float4
    int m = i >> 7;                 // / (512/4)
    int k4 = (i & 127) << 2;
    float4 v = in[i];
    __nv_bfloat162 h0 = __nv_bfloat162(__float2bfloat16_rn(v.x), __float2bfloat16_rn(v.y));
    __nv_bfloat162 h1 = __nv_bfloat162(__float2bfloat16_rn(v.z), __float2bfloat16_rn(v.w));
    __nv_bfloat162 l0 = __nv_bfloat162(__float2bfloat16_rn(v.x - __bfloat162float(h0.x)),
                                       __float2bfloat16_rn(v.y - __bfloat162float(h0.y)));
    __nv_bfloat162 l1 = __nv_bfloat162(__float2bfloat16_rn(v.z - __bfloat162float(h1.x)),
                                       __float2bfloat16_rn(v.w - __bfloat162float(h1.y)));
    __nv_bfloat16* row = g_Xcat + (size_t)m * KC;
    *(__nv_bfloat162*)(row + k4)        = h0;
    *(__nv_bfloat162*)(row + k4 + 2)    = h1;
    *(__nv_bfloat162*)(row + k4 + 512)  = l0;        // seg1: Xl (pairs with Wh)
    *(__nv_bfloat162*)(row + k4 + 514)  = l1;
    *(__nv_bfloat162*)(row + k4 + 1024) = h0;        // seg2: Xh (pairs with Wl)
    *(__nv_bfloat162*)(row + k4 + 1026) = h1;
}

// ---------------------------------------------------------------------------
// Weight transpose + split: W[K=512][N=512] float -> out[N][1536] bf16 = [hi|hi|lo]
// block (32,8), grid (16,16)
// ---------------------------------------------------------------------------
__global__ void tsplit_k(const float* __restrict__ W, __nv_bfloat16* __restrict__ out)
{
    __shared__ float t[32][33];
    int bk = blockIdx.x * 32, bn = blockIdx.y * 32;
    int tx = threadIdx.x, ty = threadIdx.y;
    #pragma unroll
    for (int i = 0; i < 32; i += 8)
        t[ty + i][tx] = W[(size_t)(bk + ty + i) * DD + bn + tx];
    __syncthreads();
    #pragma unroll
    for (int i = 0; i < 32; i += 8) {
        float v = t[tx][ty + i];
        __nv_bfloat16 h = __float2bfloat16_rn(v);
        __nv_bfloat16 l = __float2bfloat16_rn(v - __bfloat162float(h));
        size_t o = (size_t)(bn + ty + i) * KC + bk + tx;
        out[o]        = h;
        out[o + 512]  = h;
        out[o + 1024] = l;
    }
}

// ---------------------------------------------------------------------------
// B/C projection
// ---------------------------------------------------------------------------
__global__ void gemm_bc_k(const float* __restrict__ X,
                          const float* __restrict__ WB, const float* __restrict__ WC,
                          const float* __restrict__ bB, const float* __restrict__ bC)
{
    int warp = threadIdx.x >> 5, lane = threadIdx.x & 31;
    int row = blockIdx.x * 8 + warp;
    const float* Wp = (lane < NN) ? (WB + lane) : (WC + (lane - NN));
    const float* xr = X + (size_t)row * DD;
    float acc = 0.f;
    #pragma unroll 4
    for (int k = 0; k < DD; k += 4) {
        float4 xv = *(const float4*)(xr + k);
        acc = fmaf(xv.x, Wp[(k + 0) * NN], acc);
        acc = fmaf(xv.y, Wp[(k + 1) * NN], acc);
        acc = fmaf(xv.z, Wp[(k + 2) * NN], acc);
        acc = fmaf(xv.w, Wp[(k + 3) * NN], acc);
    }
    if (lane < NN) g_Bm[(size_t)row * NN + lane] = acc + bB[lane];
    else           g_Cm[(size_t)row * NN + (lane - NN)] = acc + bC[lane - NN];
}

// ---------------------------------------------------------------------------
// Scan passes
// ---------------------------------------------------------------------------
__global__ void scan1_k(const float* __restrict__ yin, const float* __restrict__ A)
{
    __shared__ float sB[LCH * NN];
    int d = blockIdx.x * 128 + threadIdx.x;
    int c = blockIdx.y, b = blockIdx.z;
    int t0 = c * LCH;

    const float4* src = (const float4*)(g_Bm + ((size_t)b * LL + t0) * NN);
    #pragma unroll
    for (int i = threadIdx.x; i < LCH * NN / 4; i += 128)
        ((float4*)sB)[i] = src[i];
    __syncthreads();

    float av[NN], h[NN], p[NN];
    #pragma unroll
    for (int q = 0; q < 4; q++)
        *(float4*)(av + q * 4) = *(const float4*)(A + (size_t)d * NN + q * 4);
    #pragma unroll
    for (int n = 0; n < NN; n++) { h[n] = 0.f; p[n] = 1.f; }

    const float* dtp = g_dt + ((size_t)b * LL + t0) * DD + d;
    const float* yp  = yin  + ((size_t)b * LL + t0) * DD + d;

    for (int t = 0; t < LCH; t++) {
        float dv = dtp[(size_t)t * DD];
        float u  = dv * yp[(size_t)t * DD];
        #pragma unroll
        for (int n = 0; n < NN; n++) {
            float e = __expf(dv * av[n]);
            p[n] *= e;
            h[n] = fmaf(e, h[n], u * sB[t * NN + n]);
        }
    }

    size_t o = (((size_t)b * NCH + c) * DD + d) * NN;
    #pragma unroll
    for (int q = 0; q < 4; q++) {
        *(float4*)(g_P  + o + q * 4) = *(float4*)(p + q * 4);
        *(float4*)(g_He + o + q * 4) = *(float4*)(h + q * 4);
    }
}

__global__ void scan2_k()
{
    int tid = blockIdx.x * blockDim.x + threadIdx.x;
    int b  = tid / (DD * NN);
    int dn = tid % (DD * NN);
    float hc = 0.f;
    for (int c = 0; c < NCH; c++) {
        size_t idx = ((size_t)(b * NCH + c)) * DD * NN + dn;
        g_carry[idx] = hc;
        hc = fmaf(g_P[idx], hc, g_He[idx]);
    }
}

__global__ void scan3_k(const float* __restrict__ yin, const float* __restrict__ A,
                        const float* __restrict__ Dskip)
{
    __shared__ float sB[LCH * NN];
    __shared__ float sC[LCH * NN];
    int d = blockIdx.x * 128 + threadIdx.x;
    int c = blockIdx.y, b = blockIdx.z;
    int t0 = c * LCH;

    {
        const float4* srcB = (const float4*)(g_Bm + ((size_t)b * LL + t0) * NN);
        const float4* srcC = (const float4*)(g_Cm + ((size_t)b * LL + t0) * NN);
        #pragma unroll
        for (int i = threadIdx.x; i < LCH * NN / 4; i += 128) {
            ((float4*)sB)[i] = srcB[i];
            ((float4*)sC)[i] = srcC[i];
        }
    }
    __syncthreads();

    float av[NN], h[NN];
    #pragma unroll
    for (int q = 0; q < 4; q++)
        *(float4*)(av + q * 4) = *(const float4*)(A + (size_t)d * NN + q * 4);
    size_t co = (((size_t)b * NCH + c) * DD + d) * NN;
    #pragma unroll
    for (int q = 0; q < 4; q++)
        *(float4*)(h + q * 4) = *(const float4*)(g_carry + co + q * 4);

    float ds = Dskip[d];
    const float* dtp = g_dt + ((size_t)b * LL + t0) * DD + d;
    const float* yp  = yin  + ((size_t)b * LL + t0) * DD + d;
    float* zp        = g_z  + ((size_t)b * LL + t0) * DD + d;

    for (int t = 0; t < LCH; t++) {
        float dv = dtp[(size_t)t * DD];
        float yv = yp[(size_t)t * DD];
        float u  = dv * yv;
        float acc = 0.f;
        #pragma unroll
        for (int n = 0; n < NN; n++) {
            float e = __expf(dv * av[n]);
            h[n] = fmaf(e, h[n], u * sB[t * NN + n]);
            acc = fmaf(h[n], sC[t * NN + n], acc);
        }
        zp[(size_t)t * DD] = fmaxf(fmaf(ds, yv, acc), 0.f);
    }
}

// ---------------------------------------------------------------------------
// Host launcher
// ---------------------------------------------------------------------------
extern "C" void kernel_launch(void* const* d_in, const int* in_sizes, int n_in,
                              void* d_out, int out_size)
{
    const float* x     = (const float*)d_in[0];
    const float* A     = (const float*)d_in[1];
    const float* Dskip = (const float*)d_in[2];
    const float* WB    = (const float*)d_in[3];
    const float* bB    = (const float*)d_in[4];
    const float* WC    = (const float*)d_in[5];
    const float* bC    = (const float*)d_in[6];
    const float* Wdt   = (const float*)d_in[7];
    const float* bdt   = (const float*)d_in[8];
    const float* Wlin  = (const float*)d_in[9];
    const float* blin  = (const float*)d_in[10];
    const float* Wdec  = (const float*)d_in[11];
    const float* bdec  = (const float*)d_in[12];
    float* out = (float*)d_out;

    float *py, *pdt, *pz;
    __nv_bfloat16 *pxc, *pwc;
    cudaGetSymbolAddress((void**)&py,  g_y);
    cudaGetSymbolAddress((void**)&pdt, g_dt);
    cudaGetSymbolAddress((void**)&pz,  g_z);
    cudaGetSymbolAddress((void**)&pxc, g_Xcat);
    cudaGetSymbolAddress((void**)&pwc, g_Wcat);

    const size_t WCSZ = (size_t)DD * KC;
    const size_t WSZ  = (size_t)DD * DD;
    dim3 tgrid(16, 16), tblk(32, 8);
    // slots: 0,1 = Wdt layers; 2,3 = Wlin layers; 4 = Wdec
    tsplit_k<<<tgrid, tblk>>>(Wdt,        pwc + 0 * WCSZ);
    tsplit_k<<<tgrid, tblk>>>(Wdt + WSZ,  pwc + 1 * WCSZ);
    tsplit_k<<<tgrid, tblk>>>(Wlin,       pwc + 2 * WCSZ);
    tsplit_k<<<tgrid, tblk>>>(Wlin + WSZ, pwc + 3 * WCSZ);
    tsplit_k<<<tgrid, tblk>>>(Wdec,       pwc + 4 * WCSZ);

    dim3 gG(DD / 128, MM / 128);   // (4, 32)
    dim3 gs(DD / 128, NCH, BB);
    int splitBlocks = (BLD / 4) / 256;

    const float* cur = x;
    for (int l = 0; l < NLAYER; l++) {
        splitx_k<<<splitBlocks, 256>>>((const float4*)cur);
        tc_gemm<1><<<gG, 256>>>(pxc, pwc + (size_t)l * WCSZ, bdt + l * DD, pdt);
        gemm_bc_k<<<(BB * LL) / 8, 256>>>(cur, WB + (size_t)l * DD * NN,
                                          WC + (size_t)l * DD * NN,
                                          bB + l * NN, bC + l * NN);
        scan1_k<<<gs, 128>>>(cur, A + (size_t)l * DD * NN);
        scan2_k<<<(BB * DD * NN) / 256, 256>>>();
        scan3_k<<<gs, 128>>>(cur, A + (size_t)l * DD * NN, Dskip + l * DD);
        splitx_k<<<splitBlocks, 256>>>((const float4*)pz);
        tc_gemm<0><<<gG, 256>>>(pxc, pwc + (size_t)(2 + l) * WCSZ, blin + l * DD, py);
        cur = py;
    }
    splitx_k<<<splitBlocks, 256>>>((const float4*)cur);
    tc_gemm<0><<<gG, 256>>>(pxc, pwc + 4 * WCSZ, bdec, out);
}

// round 4
// speedup vs baseline: 1.3787x; 1.0229x over previous
#include <cuda_runtime.h>
#include <cuda_bf16.h>
#include <math.h>
#include <cstdint>

// Problem constants
#define BB 4
#define LL 1024
#define DD 512
#define NN 16
#define OUTD 512
#define NLAYER 2
#define NCH 16
#define LCH 64

#define BLD (BB*LL*DD)
#define BLN (BB*LL*NN)
#define CHN (BB*NCH*DD*NN)

#define MM (BB*LL)      // 4096 rows
#define KC 1536         // concatenated K (3x512)

// Scratch
__device__ float g_y[BLD];
__device__ float g_dt[BLD];
__device__ float g_Bm[BLN];
__device__ float g_Cm[BLN];
__device__ float g_P[CHN];
__device__ float g_He[CHN];
__device__ float g_carry[CHN];
__device__ __nv_bfloat16 g_Xcat0[(size_t)MM * KC];       // [Xh | Xl | Xh] (read by dt/dec gemms)
__device__ __nv_bfloat16 g_Xcat1[(size_t)MM * KC];       // z split (read by lin gemm)
__device__ __nv_bfloat16 g_Wcat[5 * (size_t)DD * KC];    // per weight: [Wh | Wh | Wl] transposed [N][K]

__device__ __forceinline__ float softplusf(float x) {
    return fmaxf(x, 0.f) + log1pf(__expf(-fabsf(x)));
}

__device__ __forceinline__ uint32_t smem_u32(const void* p) {
    uint32_t a;
    asm("{ .reg .u64 t; cvta.to.shared.u64 t, %1; cvt.u32.u64 %0, t; }" : "=r"(a) : "l"(p));
    return a;
}

// swizzled byte offset inside a 128B-row tile: r = row, c = 16B chunk in [0,8)
__device__ __forceinline__ uint32_t swz(int r, int c) {
    return ((uint32_t)r << 7) + ((uint32_t)(c ^ (r & 7)) << 4);
}

// ---------------------------------------------------------------------------
// bf16 HMMA GEMM: C[M=4096, N=512] = Xcat[M, KC] @ Wcat[N, KC]^T  (TN)
// Tile 128(M) x 64(N), BK=64, 3 stages (72KB dyn smem), 256 thr, 2 CTA/SM.
// grid = (512/64=8, 4096/128=32) = 256 CTAs.
// EPI: 0=bias, 1=bias+softplus, 2=bias + also write bf16 split to xout
// ---------------------------------------------------------------------------
#define BK 64
#define STG 3
#define ABYTES 16384              // 128 rows x 128B
#define BBYTES 8192               // 64 rows x 128B
#define STAGE_BYTES (ABYTES + BBYTES)
#define TC_SMEM (STG * STAGE_BYTES)

template<int EPI>
__global__ void __launch_bounds__(256, 2)
tc_gemm(const __nv_bfloat16* __restrict__ A, const __nv_bfloat16* __restrict__ Bw,
        const float* __restrict__ bias, float* __restrict__ C,
        __nv_bfloat16* __restrict__ xout)
{
    extern __shared__ char smem[];
    uint32_t sbase = smem_u32(smem);

    int tid = threadIdx.x, wid = tid >> 5, lane = tid & 31;
    int bn = blockIdx.x * 64, bm = blockIdx.y * 128;
    int wm = wid >> 2;          // 0..1 -> m offset wm*64
    int wn = wid & 3;           // 0..3 -> n offset wn*16

    // ldmatrix swizzled offsets
    int lrow = ((lane >> 3) & 1) * 8 + (lane & 7);
    int lck = lane >> 4;
    uint32_t aoff[4][4], boff[4];
    #pragma unroll
    for (int mt = 0; mt < 4; mt++)
        #pragma unroll
        for (int ks = 0; ks < 4; ks++)
            aoff[mt][ks] = swz(wm * 64 + mt * 16 + lrow, ks * 2 + lck);
    #pragma unroll
    for (int ks = 0; ks < 4; ks++)
        boff[ks] = ABYTES + swz(wn * 16 + lrow, ks * 2 + lck);

    // cp.async mapping: A 1024 chunks (4/thread), B 512 chunks (2/thread)
    int ra = tid >> 1, ca0 = (tid & 1) * 4;
    int rb = tid >> 2, cb0 = (tid & 3) * 2;
    const __nv_bfloat16* gA = A + (size_t)(bm + ra) * KC + ca0 * 8;
    const __nv_bfloat16* gB = Bw + (size_t)(bn + rb) * KC + cb0 * 8;
    uint32_t dA[4], dB[2];
    #pragma unroll
    for (int i = 0; i < 4; i++) dA[i] = swz(ra, ca0 + i);
    #pragma unroll
    for (int i = 0; i < 2; i++) dB[i] = ABYTES + swz(rb, cb0 + i);

    float acc[4][2][4];
    #pragma unroll
    for (int i = 0; i < 4; i++)
        #pragma unroll
        for (int j = 0; j < 2; j++)
            #pragma unroll
            for (int q = 0; q < 4; q++) acc[i][j][q] = 0.f;

    const int NKB = KC / BK;    // 24

    #pragma unroll
    for (int s = 0; s < STG - 1; s++) {
        uint32_t st = sbase + s * STAGE_BYTES;
        int ko = s * BK;
        #pragma unroll
        for (int i = 0; i < 4; i++)
            asm volatile("cp.async.cg.shared.global [%0], [%1], 16;" :: "r"(st + dA[i]), "l"(gA + ko + i * 8));
        #pragma unroll
        for (int i = 0; i < 2; i++)
            asm volatile("cp.async.cg.shared.global [%0], [%1], 16;" :: "r"(st + dB[i]), "l"(gB + ko + i * 8));
        asm volatile("cp.async.commit_group;" ::: "memory");
    }

    int sbuf = 0;
    for (int kb = 0; kb < NKB; kb++) {
        asm volatile("cp.async.wait_group %0;" :: "n"(STG - 2) : "memory");
        __syncthreads();

        int knext = kb + STG - 1;
        if (knext < NKB) {
            int sn = knext % STG;
            uint32_t st = sbase + sn * STAGE_BYTES;
            int ko = knext * BK;
            #pragma unroll
            for (int i = 0; i < 4; i++)
                asm volatile("cp.async.cg.shared.global [%0], [%1], 16;" :: "r"(st + dA[i]), "l"(gA + ko + i * 8));
            #pragma unroll
            for (int i = 0; i < 2; i++)
                asm volatile("cp.async.cg.shared.global [%0], [%1], 16;" :: "r"(st + dB[i]), "l"(gB + ko + i * 8));
        }
        asm volatile("cp.async.commit_group;" ::: "memory");

        uint32_t st = sbase + sbuf * STAGE_BYTES;
        #pragma unroll
        for (int ks = 0; ks < 4; ks++) {
            uint32_t bf[4];
            asm volatile("ldmatrix.sync.aligned.m8n8.x4.shared.b16 {%0,%1,%2,%3}, [%4];"
                         : "=r"(bf[0]), "=r"(bf[1]), "=r"(bf[2]), "=r"(bf[3])
                         : "r"(st + boff[ks]));
            #pragma unroll
            for (int mt = 0; mt < 4; mt++) {
                uint32_t af[4];
                asm volatile("ldmatrix.sync.aligned.m8n8.x4.shared.b16 {%0,%1,%2,%3}, [%4];"
                             : "=r"(af[0]), "=r"(af[1]), "=r"(af[2]), "=r"(af[3])
                             : "r"(st + aoff[mt][ks]));
                #pragma unroll
                for (int nf = 0; nf < 2; nf++)
                    asm volatile(
                        "mma.sync.aligned.m16n8k16.row.col.f32.bf16.bf16.f32 "
                        "{%0,%1,%2,%3}, {%4,%5,%6,%7}, {%8,%9}, {%0,%1,%2,%3};"
                        : "+f"(acc[mt][nf][0]), "+f"(acc[mt][nf][1]),
                          "+f"(acc[mt][nf][2]), "+f"(acc[mt][nf][3])
                        : "r"(af[0]), "r"(af[1]), "r"(af[2]), "r"(af[3]),
                          "r"(bf[nf]), "r"(bf[2 + nf]));
            }
        }
        sbuf++;
        if (sbuf == STG) sbuf = 0;
    }

    // epilogue
    int mrow = bm + wm * 64 + (lane >> 2);
    int ncol = bn + wn * 16 + (lane & 3) * 2;
    #pragma unroll
    for (int mt = 0; mt < 4; mt++) {
        #pragma unroll
        for (int nf = 0; nf < 2; nf++) {
            int col = ncol + nf * 8;
            float b0 = bias[col], b1 = bias[col + 1];
            float v0 = acc[mt][nf][0] + b0, v1 = acc[mt][nf][1] + b1;
            float v2 = acc[mt][nf][2] + b0, v3 = acc[mt][nf][3] + b1;
            if (EPI == 1) { v0 = softplusf(v0); v1 = softplusf(v1); v2 = softplusf(v2); v3 = softplusf(v3); }
            int m0 = mrow + mt * 16;
            *(float2*)(C + (size_t)m0 * DD + col)       = make_float2(v0, v1);
            *(float2*)(C + (size_t)(m0 + 8) * DD + col) = make_float2(v2, v3);
            if (EPI == 2) {
                __nv_bfloat16 h0 = __float2bfloat16_rn(v0), h1 = __float2bfloat16_rn(v1);
                __nv_bfloat16 h2 = __float2bfloat16_rn(v2), h3 = __float2bfloat16_rn(v3);
                __nv_bfloat162 hv0(h0, h1), hv1(h2, h3);
                __nv_bfloat162 lv0(__float2bfloat16_rn(v0 - __bfloat162float(h0)),
                                   __float2bfloat16_rn(v1 - __bfloat162float(h1)));
                __nv_bfloat162 lv1(__float2bfloat16_rn(v2 - __bfloat162float(h2)),
                                   __float2bfloat16_rn(v3 - __bfloat162float(h3)));
                __nv_bfloat16* r0 = xout + (size_t)m0 * KC + col;
                __nv_bfloat16* r1 = xout + (size_t)(m0 + 8) * KC + col;
                *(__nv_bfloat162*)(r0)        = hv0;
                *(__nv_bfloat162*)(r0 + 512)  = lv0;
                *(__nv_bfloat162*)(r0 + 1024) = hv0;
                *(__nv_bfloat162*)(r1)        = hv1;
                *(__nv_bfloat162*)(r1 + 512)  = lv1;
                *(__nv_bfloat162*)(r1 + 1024) = hv1;
            }
        }
    }
}

// ---------------------------------------------------------------------------
// Activation split (x only): float [4096][512] -> Xcat0 bf16 [4096][1536]
// ---------------------------------------------------------------------------
__global__ void splitx_k(const float4* __restrict__ in)
{
    int i = blockIdx.x * blockDim.x + threadIdx.x;
    int m = i >> 7;
    int k4 = (i & 127) << 2;
    float4 v = in[i];
    __nv_bfloat162 h0(__float2bfloat16_rn(v.x), __float2bfloat16_rn(v.y));
    __nv_bfloat162 h1(__float2bfloat16_rn(v.z), __float2bfloat16_rn(v.w));
    __nv_bfloat162 l0(__float2bfloat16_rn(v.x - __bfloat162float(h0.x)),
                      __float2bfloat16_rn(v.y - __bfloat162float(h0.y)));
    __nv_bfloat162 l1(__float2bfloat16_rn(v.z - __bfloat162float(h1.x)),
                      __float2bfloat16_rn(v.w - __bfloat162float(h1.y)));
    __nv_bfloat16* row = g_Xcat0 + (size_t)m * KC;
    *(__nv_bfloat162*)(row + k4)        = h0;
    *(__nv_bfloat162*)(row + k4 + 2)    = h1;
    *(__nv_bfloat162*)(row + k4 + 512)  = l0;
    *(__nv_bfloat162*)(row + k4 + 514)  = l1;
    *(__nv_bfloat162*)(row + k4 + 1024) = h0;
    *(__nv_bfloat162*)(row + k4 + 1026) = h1;
}

// ---------------------------------------------------------------------------
// All 5 weight transposes+splits in one launch. blockIdx.z = slot.
// slots: 0,1 = Wdt layers; 2,3 = Wlin layers; 4 = Wdec
// ---------------------------------------------------------------------------
__global__ void tsplit_all_k(const float* __restrict__ Wdt, const float* __restrict__ Wlin,
                             const float* __restrict__ Wdec)
{
    __shared__ float t[32][33];
    int slot = blockIdx.z;
    const float* W = (slot == 0) ? Wdt
                   : (slot == 1) ? Wdt + (size_t)DD * DD
                   : (slot == 2) ? Wlin
                   : (slot == 3) ? Wlin + (size_t)DD * DD
                                 : Wdec;
    __nv_bfloat16* out = g_Wcat + (size_t)slot * DD * KC;

    int bk = blockIdx.x * 32, bn = blockIdx.y * 32;
    int tx = threadIdx.x, ty = threadIdx.y;
    #pragma unroll
    for (int i = 0; i < 32; i += 8)
        t[ty + i][tx] = W[(size_t)(bk + ty + i) * DD + bn + tx];
    __syncthreads();
    #pragma unroll
    for (int i = 0; i < 32; i += 8) {
        float v = t[tx][ty + i];
        __nv_bfloat16 h = __float2bfloat16_rn(v);
        __nv_bfloat16 l = __float2bfloat16_rn(v - __bfloat162float(h));
        size_t o = (size_t)(bn + ty + i) * KC + bk + tx;
        out[o]        = h;
        out[o + 512]  = h;
        out[o + 1024] = l;
    }
}

// ---------------------------------------------------------------------------
// B/C projection
// ---------------------------------------------------------------------------
__global__ void gemm_bc_k(const float* __restrict__ X,
                          const float* __restrict__ WB, const float* __restrict__ WC,
                          const float* __restrict__ bB, const float* __restrict__ bC)
{
    int warp = threadIdx.x >> 5, lane = threadIdx.x & 31;
    int row = blockIdx.x * 8 + warp;
    const float* Wp = (lane < NN) ? (WB + lane) : (WC + (lane - NN));
    const float* xr = X + (size_t)row * DD;
    float acc = 0.f;
    #pragma unroll 4
    for (int k = 0; k < DD; k += 4) {
        float4 xv = *(const float4*)(xr + k);
        acc = fmaf(xv.x, Wp[(k + 0) * NN], acc);
        acc = fmaf(xv.y, Wp[(k + 1) * NN], acc);
        acc = fmaf(xv.z, Wp[(k + 2) * NN], acc);
        acc = fmaf(xv.w, Wp[(k + 3) * NN], acc);
    }
    if (lane < NN) g_Bm[(size_t)row * NN + lane] = acc + bB[lane];
    else           g_Cm[(size_t)row * NN + (lane - NN)] = acc + bC[lane - NN];
}

// ---------------------------------------------------------------------------
// Scan pass 1: local chunk scan from zero; store P, He.
// grid = (4, 16, 4), block 128
// ---------------------------------------------------------------------------
__global__ void scan1_k(const float* __restrict__ yin, const float* __restrict__ A)
{
    __shared__ float sB[LCH * NN];
    int d = blockIdx.x * 128 + threadIdx.x;
    int c = blockIdx.y, b = blockIdx.z;
    int t0 = c * LCH;

    const float4* src = (const float4*)(g_Bm + ((size_t)b * LL + t0) * NN);
    #pragma unroll
    for (int i = threadIdx.x; i < LCH * NN / 4; i += 128)
        ((float4*)sB)[i] = src[i];
    __syncthreads();

    float av[NN], h[NN], p[NN];
    #pragma unroll
    for (int q = 0; q < 4; q++)
        *(float4*)(av + q * 4) = *(const float4*)(A + (size_t)d * NN + q * 4);
    #pragma unroll
    for (int n = 0; n < NN; n++) { h[n] = 0.f; p[n] = 1.f; }

    const float* dtp = g_dt + ((size_t)b * LL + t0) * DD + d;
    const float* yp  = yin  + ((size_t)b * LL + t0) * DD + d;

    for (int t = 0; t < LCH; t++) {
        float dv = dtp[(size_t)t * DD];
        float u  = dv * yp[(size_t)t * DD];
        #pragma unroll
        for (int n = 0; n < NN; n++) {
            float e = __expf(dv * av[n]);
            p[n] *= e;
            h[n] = fmaf(e, h[n], u * sB[t * NN + n]);
        }
    }

    size_t o = (((size_t)b * NCH + c) * DD + d) * NN;
    #pragma unroll
    for (int q = 0; q < 4; q++) {
        *(float4*)(g_P  + o + q * 4) = *(float4*)(p + q * 4);
        *(float4*)(g_He + o + q * 4) = *(float4*)(h + q * 4);
    }
}

// ---------------------------------------------------------------------------
// Scan pass 2: batch all chunk loads into registers (MLP), then combine.
// grid = 128, block 256 (B*D*N = 32768 threads)
// ---------------------------------------------------------------------------
__global__ void scan2_k()
{
    int tid = blockIdx.x * blockDim.x + threadIdx.x;
    int b  = tid >> 13;            // / (DD*NN = 8192)
    int dn = tid & 8191;
    size_t base = (size_t)b * NCH * DD * NN + dn;

    float p[NCH], he[NCH];
    #pragma unroll
    for (int c = 0; c < NCH; c++) {
        p[c]  = g_P [base + (size_t)c * DD * NN];
        he[c] = g_He[base + (size_t)c * DD * NN];
    }
    float hc = 0.f;
    float cr[NCH];
    #pragma unroll
    for (int c = 0; c < NCH; c++) {
        cr[c] = hc;
        hc = fmaf(p[c], hc, he[c]);
    }
    #pragma unroll
    for (int c = 0; c < NCH; c++)
        g_carry[base + (size_t)c * DD * NN] = cr[c];
}

// ---------------------------------------------------------------------------
// Scan pass 3: rescan with carry; write z directly as bf16 split into Xcat1.
// grid = (4, 16, 4), block 128
// ---------------------------------------------------------------------------
__global__ void scan3_k(const float* __restrict__ yin, const float* __restrict__ A,
                        const float* __restrict__ Dskip)
{
    __shared__ float sB[LCH * NN];
    __shared__ float sC[LCH * NN];
    int d = blockIdx.x * 128 + threadIdx.x;
    int c = blockIdx.y, b = blockIdx.z;
    int t0 = c * LCH;

    {
        const float4* srcB = (const float4*)(g_Bm + ((size_t)b * LL + t0) * NN);
        const float4* srcC = (const float4*)(g_Cm + ((size_t)b * LL + t0) * NN);
        #pragma unroll
        for (int i = threadIdx.x; i < LCH * NN / 4; i += 128) {
            ((float4*)sB)[i] = srcB[i];
            ((float4*)sC)[i] = srcC[i];
        }
    }
    __syncthreads();

    float av[NN], h[NN];
    #pragma unroll
    for (int q = 0; q < 4; q++)
        *(float4*)(av + q * 4) = *(const float4*)(A + (size_t)d * NN + q * 4);
    size_t co = (((size_t)b * NCH + c) * DD + d) * NN;
    #pragma unroll
    for (int q = 0; q < 4; q++)
        *(float4*)(h + q * 4) = *(const float4*)(g_carry + co + q * 4);

    float ds = Dskip[d];
    const float* dtp = g_dt + ((size_t)b * LL + t0) * DD + d;
    const float* yp  = yin  + ((size_t)b * LL + t0) * DD + d;
    __nv_bfloat16* zb = g_Xcat1 + ((size_t)b * LL + t0) * KC + d;

    for (int t = 0; t < LCH; t++) {
        float dv = dtp[(size_t)t * DD];
        float yv = yp[(size_t)t * DD];
        float u  = dv * yv;
        float acc = 0.f;
        #pragma unroll
        for (int n = 0; n < NN; n++) {
            float e = __expf(dv * av[n]);
            h[n] = fmaf(e, h[n], u * sB[t * NN + n]);
            acc = fmaf(h[n], sC[t * NN + n], acc);
        }
        float z = fmaxf(fmaf(ds, yv, acc), 0.f);
        __nv_bfloat16 hi = __float2bfloat16_rn(z);
        __nv_bfloat16 lo = __float2bfloat16_rn(z - __bfloat162float(hi));
        __nv_bfloat16* zr = zb + (size_t)t * KC;
        zr[0]    = hi;
        zr[512]  = lo;
        zr[1024] = hi;
    }
}

// ---------------------------------------------------------------------------
// Host launcher
// ---------------------------------------------------------------------------
extern "C" void kernel_launch(void* const* d_in, const int* in_sizes, int n_in,
                              void* d_out, int out_size)
{
    const float* x     = (const float*)d_in[0];
    const float* A     = (const float*)d_in[1];
    const float* Dskip = (const float*)d_in[2];
    const float* WB    = (const float*)d_in[3];
    const float* bB    = (const float*)d_in[4];
    const float* WC    = (const float*)d_in[5];
    const float* bC    = (const float*)d_in[6];
    const float* Wdt   = (const float*)d_in[7];
    const float* bdt   = (const float*)d_in[8];
    const float* Wlin  = (const float*)d_in[9];
    const float* blin  = (const float*)d_in[10];
    const float* Wdec  = (const float*)d_in[11];
    const float* bdec  = (const float*)d_in[12];
    float* out = (float*)d_out;

    float *py, *pdt;
    __nv_bfloat16 *px0, *px1, *pwc;
    cudaGetSymbolAddress((void**)&py,  g_y);
    cudaGetSymbolAddress((void**)&pdt, g_dt);
    cudaGetSymbolAddress((void**)&px0, g_Xcat0);
    cudaGetSymbolAddress((void**)&px1, g_Xcat1);
    cudaGetSymbolAddress((void**)&pwc, g_Wcat);

    cudaFuncSetAttribute(tc_gemm<0>, cudaFuncAttributeMaxDynamicSharedMemorySize, TC_SMEM);
    cudaFuncSetAttribute(tc_gemm<1>, cudaFuncAttributeMaxDynamicSharedMemorySize, TC_SMEM);
    cudaFuncSetAttribute(tc_gemm<2>, cudaFuncAttributeMaxDynamicSharedMemorySize, TC_SMEM);

    const size_t WCSZ = (size_t)DD * KC;

    dim3 tgrid(16, 16, 5), tblk(32, 8);
    tsplit_all_k<<<tgrid, tblk>>>(Wdt, Wlin, Wdec);

    dim3 gG(DD / 64, MM / 128);   // (8, 32) = 256 CTAs
    dim3 gs(DD / 128, NCH, BB);

    splitx_k<<<(BLD / 4) / 256, 256>>>((const float4*)x);

    const float* cur = x;
    for (int l = 0; l < NLAYER; l++) {
        tc_gemm<1><<<gG, 256, TC_SMEM>>>(px0, pwc + (size_t)l * WCSZ, bdt + l * DD, pdt, nullptr);
        gemm_bc_k<<<(BB * LL) / 8, 256>>>(cur, WB + (size_t)l * DD * NN,
                                          WC + (size_t)l * DD * NN,
                                          bB + l * NN, bC + l * NN);
        scan1_k<<<gs, 128>>>(cur, A + (size_t)l * DD * NN);
        scan2_k<<<(BB * DD * NN) / 256, 256>>>();
        scan3_k<<<gs, 128>>>(cur, A + (size_t)l * DD * NN, Dskip + l * DD);   // -> Xcat1
        tc_gemm<2><<<gG, 256, TC_SMEM>>>(px1, pwc + (size_t)(2 + l) * WCSZ, blin + l * DD, py, px0);
        cur = py;
    }
    tc_gemm<0><<<gG, 256, TC_SMEM>>>(px0, pwc + 4 * WCSZ, bdec, out, nullptr);
}

// round 5
// speedup vs baseline: 1.6150x; 1.1714x over previous
#include <cuda_runtime.h>
#include <cuda_bf16.h>
#include <math.h>
#include <cstdint>

// Problem constants
#define BB 4
#define LL 1024
#define DD 512
#define NN 16
#define OUTD 512
#define NLAYER 2
#define NCH 16
#define LCH 64

#define BLD (BB*LL*DD)
#define BLN (BB*LL*NN)
#define CHN (BB*NCH*DD*NN)

#define MM (BB*LL)      // 4096 rows
#define KC 1536         // concatenated K (3x512)
#define NW 576          // widened N for fused dt+B+C gemm (512 + 16 + 16 + 32 pad)

// Scratch
__device__ float g_y[BLD];
__device__ float g_dt[BLD];
__device__ float g_Bm[BLN];
__device__ float g_Cm[BLN];
__device__ float g_P[CHN];
__device__ float g_He[CHN];
__device__ float g_carry[CHN];
__device__ __nv_bfloat16 g_Xcat0[(size_t)MM * KC];       // [Xh | Xl | Xh]
__device__ __nv_bfloat16 g_Xcat1[(size_t)MM * KC];       // z split
__device__ __nv_bfloat16 g_Wcat[5 * (size_t)NW * KC];    // [hi|hi|lo], transposed [N][K], 576-row slots

__device__ __forceinline__ float softplusf(float x) {
    return fmaxf(x, 0.f) + log1pf(__expf(-fabsf(x)));
}

__device__ __forceinline__ uint32_t smem_u32(const void* p) {
    uint32_t a;
    asm("{ .reg .u64 t; cvta.to.shared.u64 t, %1; cvt.u32.u64 %0, t; }" : "=r"(a) : "l"(p));
    return a;
}

// swizzled byte offset inside a 128B-row tile: r = row, c = 16B chunk in [0,8)
__device__ __forceinline__ uint32_t swz(int r, int c) {
    return ((uint32_t)r << 7) + ((uint32_t)(c ^ (r & 7)) << 4);
}

// ---------------------------------------------------------------------------
// bf16 HMMA GEMM, software-pipelined ldmatrix.
// C[M=4096, Ncols] = Xcat[M, KC] @ Wcat[Ncols, KC]^T  (TN)
// Tile 128(M) x 64(N), BK=64, 3 stages, 256 thr, 2 CTA/SM.
// EPI 0: bias (N=512)                  grid (8, 32)
// EPI 1: dt softplus + Bm/Cm fused     grid (9, 32)
// EPI 2: bias + bf16-split to xout     grid (8, 32)
// ---------------------------------------------------------------------------
#define BK 64
#define STG 3
#define ABYTES 16384
#define BBYTES 8192
#define STAGE_BYTES (ABYTES + BBYTES)
#define TC_SMEM (STG * STAGE_BYTES)

template<int EPI>
__global__ void __launch_bounds__(256, 2)
tc_gemm(const __nv_bfloat16* __restrict__ A, const __nv_bfloat16* __restrict__ Bw,
        const float* __restrict__ bias, const float* __restrict__ bB,
        const float* __restrict__ bC, float* __restrict__ C,
        __nv_bfloat16* __restrict__ xout)
{
    extern __shared__ char smem[];
    uint32_t sbase = smem_u32(smem);

    int tid = threadIdx.x, wid = tid >> 5, lane = tid & 31;
    int bn = blockIdx.x * 64, bm = blockIdx.y * 128;
    int wm = wid >> 2;          // 0..1
    int wn = wid & 3;           // 0..3

    int lrow = ((lane >> 3) & 1) * 8 + (lane & 7);
    int lck = lane >> 4;
    uint32_t aoff[4][4], boff[4];
    #pragma unroll
    for (int mt = 0; mt < 4; mt++)
        #pragma unroll
        for (int ks = 0; ks < 4; ks++)
            aoff[mt][ks] = swz(wm * 64 + mt * 16 + lrow, ks * 2 + lck);
    #pragma unroll
    for (int ks = 0; ks < 4; ks++)
        boff[ks] = ABYTES + swz(wn * 16 + lrow, ks * 2 + lck);

    int ra = tid >> 1, ca0 = (tid & 1) * 4;
    int rb = tid >> 2, cb0 = (tid & 3) * 2;
    const __nv_bfloat16* gA = A + (size_t)(bm + ra) * KC + ca0 * 8;
    const __nv_bfloat16* gB = Bw + (size_t)(bn + rb) * KC + cb0 * 8;
    uint32_t dA[4], dB[2];
    #pragma unroll
    for (int i = 0; i < 4; i++) dA[i] = swz(ra, ca0 + i);
    #pragma unroll
    for (int i = 0; i < 2; i++) dB[i] = ABYTES + swz(rb, cb0 + i);

    float acc[4][2][4];
    #pragma unroll
    for (int i = 0; i < 4; i++)
        #pragma unroll
        for (int j = 0; j < 2; j++)
            #pragma unroll
            for (int q = 0; q < 4; q++) acc[i][j][q] = 0.f;

    const int NKB = KC / BK;    // 24

    #pragma unroll
    for (int s = 0; s < STG - 1; s++) {
        uint32_t st = sbase + s * STAGE_BYTES;
        int ko = s * BK;
        #pragma unroll
        for (int i = 0; i < 4; i++)
            asm volatile("cp.async.cg.shared.global [%0], [%1], 16;" :: "r"(st + dA[i]), "l"(gA + ko + i * 8));
        #pragma unroll
        for (int i = 0; i < 2; i++)
            asm volatile("cp.async.cg.shared.global [%0], [%1], 16;" :: "r"(st + dB[i]), "l"(gB + ko + i * 8));
        asm volatile("cp.async.commit_group;" ::: "memory");
    }

    uint32_t bufA[2][4][4], bufB[2][4];

    int sbuf = 0;
    for (int kb = 0; kb < NKB; kb++) {
        asm volatile("cp.async.wait_group %0;" :: "n"(STG - 2) : "memory");
        __syncthreads();

        int knext = kb + STG - 1;
        if (knext < NKB) {
            int sn = knext % STG;
            uint32_t st = sbase + sn * STAGE_BYTES;
            int ko = knext * BK;
            #pragma unroll
            for (int i = 0; i < 4; i++)
                asm volatile("cp.async.cg.shared.global [%0], [%1], 16;" :: "r"(st + dA[i]), "l"(gA + ko + i * 8));
            #pragma unroll
            for (int i = 0; i < 2; i++)
                asm volatile("cp.async.cg.shared.global [%0], [%1], 16;" :: "r"(st + dB[i]), "l"(gB + ko + i * 8));
        }
        asm volatile("cp.async.commit_group;" ::: "memory");

        uint32_t st = sbase + sbuf * STAGE_BYTES;

        // prime ks=0 operands
        asm volatile("ldmatrix.sync.aligned.m8n8.x4.shared.b16 {%0,%1,%2,%3}, [%4];"
                     : "=r"(bufB[0][0]), "=r"(bufB[0][1]), "=r"(bufB[0][2]), "=r"(bufB[0][3])
                     : "r"(st + boff[0]));
        #pragma unroll
        for (int mt = 0; mt < 4; mt++)
            asm volatile("ldmatrix.sync.aligned.m8n8.x4.shared.b16 {%0,%1,%2,%3}, [%4];"
                         : "=r"(bufA[0][mt][0]), "=r"(bufA[0][mt][1]),
                           "=r"(bufA[0][mt][2]), "=r"(bufA[0][mt][3])
                         : "r"(st + aoff[mt][0]));

        #pragma unroll
        for (int ks = 0; ks < 4; ks++) {
            int cb = ks & 1, nb = cb ^ 1;
            if (ks < 3) {
                asm volatile("ldmatrix.sync.aligned.m8n8.x4.shared.b16 {%0,%1,%2,%3}, [%4];"
                             : "=r"(bufB[nb][0]), "=r"(bufB[nb][1]), "=r"(bufB[nb][2]), "=r"(bufB[nb][3])
                             : "r"(st + boff[ks + 1]));
                #pragma unroll
                for (int mt = 0; mt < 4; mt++)
                    asm volatile("ldmatrix.sync.aligned.m8n8.x4.shared.b16 {%0,%1,%2,%3}, [%4];"
                                 : "=r"(bufA[nb][mt][0]), "=r"(bufA[nb][mt][1]),
                                   "=r"(bufA[nb][mt][2]), "=r"(bufA[nb][mt][3])
                                 : "r"(st + aoff[mt][ks + 1]));
            }
            #pragma unroll
            for (int mt = 0; mt < 4; mt++)
                #pragma unroll
                for (int nf = 0; nf < 2; nf++)
                    asm volatile(
                        "mma.sync.aligned.m16n8k16.row.col.f32.bf16.bf16.f32 "
                        "{%0,%1,%2,%3}, {%4,%5,%6,%7}, {%8,%9}, {%0,%1,%2,%3};"
                        : "+f"(acc[mt][nf][0]), "+f"(acc[mt][nf][1]),
                          "+f"(acc[mt][nf][2]), "+f"(acc[mt][nf][3])
                        : "r"(bufA[cb][mt][0]), "r"(bufA[cb][mt][1]),
                          "r"(bufA[cb][mt][2]), "r"(bufA[cb][mt][3]),
                          "r"(bufB[cb][nf]), "r"(bufB[cb][2 + nf]));
        }
        sbuf++;
        if (sbuf == STG) sbuf = 0;
    }

    // epilogue
    int mrow = bm + wm * 64 + (lane >> 2);
    int ncol = bn + wn * 16 + (lane & 3) * 2;
    #pragma unroll
    for (int mt = 0; mt < 4; mt++) {
        #pragma unroll
        for (int nf = 0; nf < 2; nf++) {
            int col = ncol + nf * 8;
            int m0 = mrow + mt * 16;
            float b0, b1;
            if (EPI == 1 && col >= 512) {
                if (col < 528)      { b0 = bB[col - 512]; b1 = bB[col - 511]; }
                else if (col < 544) { b0 = bC[col - 528]; b1 = bC[col - 527]; }
                else                { b0 = 0.f; b1 = 0.f; }
            } else {
                b0 = bias[col]; b1 = bias[col + 1];
            }
            float v0 = acc[mt][nf][0] + b0, v1 = acc[mt][nf][1] + b1;
            float v2 = acc[mt][nf][2] + b0, v3 = acc[mt][nf][3] + b1;

            if (EPI == 1 && col >= 512) {
                if (col < 528) {
                    int n = col - 512;
                    *(float2*)(g_Bm + (size_t)m0 * NN + n)       = make_float2(v0, v1);
                    *(float2*)(g_Bm + (size_t)(m0 + 8) * NN + n) = make_float2(v2, v3);
                } else if (col < 544) {
                    int n = col - 528;
                    *(float2*)(g_Cm + (size_t)m0 * NN + n)       = make_float2(v0, v1);
                    *(float2*)(g_Cm + (size_t)(m0 + 8) * NN + n) = make_float2(v2, v3);
                }
                continue;
            }
            if (EPI == 1) { v0 = softplusf(v0); v1 = softplusf(v1); v2 = softplusf(v2); v3 = softplusf(v3); }
            *(float2*)(C + (size_t)m0 * DD + col)       = make_float2(v0, v1);
            *(float2*)(C + (size_t)(m0 + 8) * DD + col) = make_float2(v2, v3);
            if (EPI == 2) {
                __nv_bfloat16 h0 = __float2bfloat16_rn(v0), h1 = __float2bfloat16_rn(v1);
                __nv_bfloat16 h2 = __float2bfloat16_rn(v2), h3 = __float2bfloat16_rn(v3);
                __nv_bfloat162 hv0(h0, h1), hv1(h2, h3);
                __nv_bfloat162 lv0(__float2bfloat16_rn(v0 - __bfloat162float(h0)),
                                   __float2bfloat16_rn(v1 - __bfloat162float(h1)));
                __nv_bfloat162 lv1(__float2bfloat16_rn(v2 - __bfloat162float(h2)),
                                   __float2bfloat16_rn(v3 - __bfloat162float(h3)));
                __nv_bfloat16* r0 = xout + (size_t)m0 * KC + col;
                __nv_bfloat16* r1 = xout + (size_t)(m0 + 8) * KC + col;
                *(__nv_bfloat162*)(r0)        = hv0;
                *(__nv_bfloat162*)(r0 + 512)  = lv0;
                *(__nv_bfloat162*)(r0 + 1024) = hv0;
                *(__nv_bfloat162*)(r1)        = hv1;
                *(__nv_bfloat162*)(r1 + 512)  = lv1;
                *(__nv_bfloat162*)(r1 + 1024) = hv1;
            }
        }
    }
}

// ---------------------------------------------------------------------------
// Activation split (x only)
// ---------------------------------------------------------------------------
__global__ void splitx_k(const float4* __restrict__ in)
{
    int i = blockIdx.x * blockDim.x + threadIdx.x;
    int m = i >> 7;
    int k4 = (i & 127) << 2;
    float4 v = in[i];
    __nv_bfloat162 h0(__float2bfloat16_rn(v.x), __float2bfloat16_rn(v.y));
    __nv_bfloat162 h1(__float2bfloat16_rn(v.z), __float2bfloat16_rn(v.w));
    __nv_bfloat162 l0(__float2bfloat16_rn(v.x - __bfloat162float(h0.x)),
                      __float2bfloat16_rn(v.y - __bfloat162float(h0.y)));
    __nv_bfloat162 l1(__float2bfloat16_rn(v.z - __bfloat162float(h1.x)),
                      __float2bfloat16_rn(v.w - __bfloat162float(h1.y)));
    __nv_bfloat16* row = g_Xcat0 + (size_t)m * KC;
    *(__nv_bfloat162*)(row + k4)        = h0;
    *(__nv_bfloat162*)(row + k4 + 2)    = h1;
    *(__nv_bfloat162*)(row + k4 + 512)  = l0;
    *(__nv_bfloat162*)(row + k4 + 514)  = l1;
    *(__nv_bfloat162*)(row + k4 + 1024) = h0;
    *(__nv_bfloat162*)(row + k4 + 1026) = h1;
}

// ---------------------------------------------------------------------------
// Big-weight transpose+split (rows 0..511 of each slot). blockIdx.z = slot.
// ---------------------------------------------------------------------------
__global__ void tsplit_all_k(const float* __restrict__ Wdt, const float* __restrict__ Wlin,
                             const float* __restrict__ Wdec)
{
    __shared__ float t[32][33];
    int slot = blockIdx.z;
    const float* W = (slot == 0) ? Wdt
                   : (slot == 1) ? Wdt + (size_t)DD * DD
                   : (slot == 2) ? Wlin
                   : (slot == 3) ? Wlin + (size_t)DD * DD
                                 : Wdec;
    __nv_bfloat16* out = g_Wcat + (size_t)slot * NW * KC;

    int bk = blockIdx.x * 32, bn = blockIdx.y * 32;
    int tx = threadIdx.x, ty = threadIdx.y;
    #pragma unroll
    for (int i = 0; i < 32; i += 8)
        t[ty + i][tx] = W[(size_t)(bk + ty + i) * DD + bn + tx];
    __syncthreads();
    #pragma unroll
    for (int i = 0; i < 32; i += 8) {
        float v = t[tx][ty + i];
        __nv_bfloat16 h = __float2bfloat16_rn(v);
        __nv_bfloat16 l = __float2bfloat16_rn(v - __bfloat162float(h));
        size_t o = (size_t)(bn + ty + i) * KC + bk + tx;
        out[o]        = h;
        out[o + 512]  = h;
        out[o + 1024] = l;
    }
}

// ---------------------------------------------------------------------------
// WB/WC transpose+split into rows 512..575 of dt slots (0,1).
// grid (16 kblocks, 2 layers), block (32, 8). rows 0..15 WB, 16..31 WC, 32..63 zero.
// ---------------------------------------------------------------------------
__global__ void tsplit_bc_k(const float* __restrict__ WB, const float* __restrict__ WC)
{
    int l = blockIdx.y;
    int bk = blockIdx.x * 32;
    int tx = threadIdx.x;                 // k within block
    __nv_bfloat16* out = g_Wcat + (size_t)l * NW * KC + (size_t)512 * KC;

    for (int r = threadIdx.y; r < 64; r += 8) {
        float v = 0.f;
        if (r < 16)      v = WB[(size_t)l * DD * NN + (size_t)(bk + tx) * NN + r];
        else if (r < 32) v = WC[(size_t)l * DD * NN + (size_t)(bk + tx) * NN + (r - 16)];
        __nv_bfloat16 h = __float2bfloat16_rn(v);
        __nv_bfloat16 lo = __float2bfloat16_rn(v - __bfloat162float(h));
        size_t o = (size_t)r * KC + bk + tx;
        out[o]        = h;
        out[o + 512]  = h;
        out[o + 1024] = lo;
    }
}

// ---------------------------------------------------------------------------
// Scan pass 1
// ---------------------------------------------------------------------------
__global__ void scan1_k(const float* __restrict__ yin, const float* __restrict__ A)
{
    __shared__ float sB[LCH * NN];
    int d = blockIdx.x * 128 + threadIdx.x;
    int c = blockIdx.y, b = blockIdx.z;
    int t0 = c * LCH;

    const float4* src = (const float4*)(g_Bm + ((size_t)b * LL + t0) * NN);
    #pragma unroll
    for (int i = threadIdx.x; i < LCH * NN / 4; i += 128)
        ((float4*)sB)[i] = src[i];
    __syncthreads();

    float av[NN], h[NN], p[NN];
    #pragma unroll
    for (int q = 0; q < 4; q++)
        *(float4*)(av + q * 4) = *(const float4*)(A + (size_t)d * NN + q * 4);
    #pragma unroll
    for (int n = 0; n < NN; n++) { h[n] = 0.f; p[n] = 1.f; }

    const float* dtp = g_dt + ((size_t)b * LL + t0) * DD + d;
    const float* yp  = yin  + ((size_t)b * LL + t0) * DD + d;

    for (int t = 0; t < LCH; t++) {
        float dv = dtp[(size_t)t * DD];
        float u  = dv * yp[(size_t)t * DD];
        #pragma unroll
        for (int n = 0; n < NN; n++) {
            float e = __expf(dv * av[n]);
            p[n] *= e;
            h[n] = fmaf(e, h[n], u * sB[t * NN + n]);
        }
    }

    size_t o = (((size_t)b * NCH + c) * DD + d) * NN;
    #pragma unroll
    for (int q = 0; q < 4; q++) {
        *(float4*)(g_P  + o + q * 4) = *(float4*)(p + q * 4);
        *(float4*)(g_He + o + q * 4) = *(float4*)(h + q * 4);
    }
}

// ---------------------------------------------------------------------------
// Scan pass 2 (batched loads)
// ---------------------------------------------------------------------------
__global__ void scan2_k()
{
    int tid = blockIdx.x * blockDim.x + threadIdx.x;
    int b  = tid >> 13;
    int dn = tid & 8191;
    size_t base = (size_t)b * NCH * DD * NN + dn;

    float p[NCH], he[NCH];
    #pragma unroll
    for (int c = 0; c < NCH; c++) {
        p[c]  = g_P [base + (size_t)c * DD * NN];
        he[c] = g_He[base + (size_t)c * DD * NN];
    }
    float hc = 0.f;
    float cr[NCH];
    #pragma unroll
    for (int c = 0; c < NCH; c++) {
        cr[c] = hc;
        hc = fmaf(p[c], hc, he[c]);
    }
    #pragma unroll
    for (int c = 0; c < NCH; c++)
        g_carry[base + (size_t)c * DD * NN] = cr[c];
}

// ---------------------------------------------------------------------------
// Scan pass 3: rescan with carry; write z as bf16 split into Xcat1.
// ---------------------------------------------------------------------------
__global__ void scan3_k(const float* __restrict__ yin, const float* __restrict__ A,
                        const float* __restrict__ Dskip)
{
    __shared__ float sB[LCH * NN];
    __shared__ float sC[LCH * NN];
    int d = blockIdx.x * 128 + threadIdx.x;
    int c = blockIdx.y, b = blockIdx.z;
    int t0 = c * LCH;

    {
        const float4* srcB = (const float4*)(g_Bm + ((size_t)b * LL + t0) * NN);
        const float4* srcC = (const float4*)(g_Cm + ((size_t)b * LL + t0) * NN);
        #pragma unroll
        for (int i = threadIdx.x; i < LCH * NN / 4; i += 128) {
            ((float4*)sB)[i] = srcB[i];
            ((float4*)sC)[i] = srcC[i];
        }
    }
    __syncthreads();

    float av[NN], h[NN];
    #pragma unroll
    for (int q = 0; q < 4; q++)
        *(float4*)(av + q * 4) = *(const float4*)(A + (size_t)d * NN + q * 4);
    size_t co = (((size_t)b * NCH + c) * DD + d) * NN;
    #pragma unroll
    for (int q = 0; q < 4; q++)
        *(float4*)(h + q * 4) = *(const float4*)(g_carry + co + q * 4);

    float ds = Dskip[d];
    const float* dtp = g_dt + ((size_t)b * LL + t0) * DD + d;
    const float* yp  = yin  + ((size_t)b * LL + t0) * DD + d;
    __nv_bfloat16* zb = g_Xcat1 + ((size_t)b * LL + t0) * KC + d;

    for (int t = 0; t < LCH; t++) {
        float dv = dtp[(size_t)t * DD];
        float yv = yp[(size_t)t * DD];
        float u  = dv * yv;
        float acc = 0.f;
        #pragma unroll
        for (int n = 0; n < NN; n++) {
            float e = __expf(dv * av[n]);
            h[n] = fmaf(e, h[n], u * sB[t * NN + n]);
            acc = fmaf(h[n], sC[t * NN + n], acc);
        }
        float z = fmaxf(fmaf(ds, yv, acc), 0.f);
        __nv_bfloat16 hi = __float2bfloat16_rn(z);
        __nv_bfloat16 lo = __float2bfloat16_rn(z - __bfloat162float(hi));
        __nv_bfloat16* zr = zb + (size_t)t * KC;
        zr[0]    = hi;
        zr[512]  = lo;
        zr[1024] = hi;
    }
}

// ---------------------------------------------------------------------------
// Host launcher
// ---------------------------------------------------------------------------
extern "C" void kernel_launch(void* const* d_in, const int* in_sizes, int n_in,
                              void* d_out, int out_size)
{
    const float* x     = (const float*)d_in[0];
    const float* A     = (const float*)d_in[1];
    const float* Dskip = (const float*)d_in[2];
    const float* WB    = (const float*)d_in[3];
    const float* bB    = (const float*)d_in[4];
    const float* WC    = (const float*)d_in[5];
    const float* bC    = (const float*)d_in[6];
    const float* Wdt   = (const float*)d_in[7];
    const float* bdt   = (const float*)d_in[8];
    const float* Wlin  = (const float*)d_in[9];
    const float* blin  = (const float*)d_in[10];
    const float* Wdec  = (const float*)d_in[11];
    const float* bdec  = (const float*)d_in[12];
    float* out = (float*)d_out;

    float *py, *pdt;
    __nv_bfloat16 *px0, *px1, *pwc;
    cudaGetSymbolAddress((void**)&py,  g_y);
    cudaGetSymbolAddress((void**)&pdt, g_dt);
    cudaGetSymbolAddress((void**)&px0, g_Xcat0);
    cudaGetSymbolAddress((void**)&px1, g_Xcat1);
    cudaGetSymbolAddress((void**)&pwc, g_Wcat);

    cudaFuncSetAttribute(tc_gemm<0>, cudaFuncAttributeMaxDynamicSharedMemorySize, TC_SMEM);
    cudaFuncSetAttribute(tc_gemm<1>, cudaFuncAttributeMaxDynamicSharedMemorySize, TC_SMEM);
    cudaFuncSetAttribute(tc_gemm<2>, cudaFuncAttributeMaxDynamicSharedMemorySize, TC_SMEM);

    const size_t WCSZ = (size_t)NW * KC;

    dim3 tgrid(16, 16, 5), tblk(32, 8);
    tsplit_all_k<<<tgrid, tblk>>>(Wdt, Wlin, Wdec);
    tsplit_bc_k<<<dim3(16, 2), tblk>>>(WB, WC);

    dim3 gG1(NW / 64, MM / 128);   // (9, 32) fused dt+BC
    dim3 gG(DD / 64, MM / 128);    // (8, 32)
    dim3 gs(DD / 128, NCH, BB);

    splitx_k<<<(BLD / 4) / 256, 256>>>((const float4*)x);

    const float* cur = x;
    for (int l = 0; l < NLAYER; l++) {
        tc_gemm<1><<<gG1, 256, TC_SMEM>>>(px0, pwc + (size_t)l * WCSZ, bdt + l * DD,
                                          bB + l * NN, bC + l * NN, pdt, nullptr);
        scan1_k<<<gs, 128>>>(cur, A + (size_t)l * DD * NN);
        scan2_k<<<(BB * DD * NN) / 256, 256>>>();
        scan3_k<<<gs, 128>>>(cur, A + (size_t)l * DD * NN, Dskip + l * DD);
        tc_gemm<2><<<gG, 256, TC_SMEM>>>(px1, pwc + (size_t)(2 + l) * WCSZ, blin + l * DD,
                                         nullptr, nullptr, py, px0);
        cur = py;
    }
    tc_gemm<0><<<gG, 256, TC_SMEM>>>(px0, pwc + 4 * WCSZ, bdec, nullptr, nullptr, out, nullptr);
}

// round 6
// speedup vs baseline: 1.6278x; 1.0079x over previous
#include <cuda_runtime.h>
#include <cuda_bf16.h>
#include <math.h>
#include <cstdint>

// Problem constants
#define BB 4
#define LL 1024
#define DD 512
#define NN 16
#define OUTD 512
#define NLAYER 2
#define NCH 16
#define LCH 64

#define BLD (BB*LL*DD)
#define BLN (BB*LL*NN)
#define CHN (BB*NCH*DD*NN)

#define MM (BB*LL)      // 4096 rows
#define KC 1536         // concatenated K (3x512)
#define NW 576          // widened N for fused dt+B+C gemm

// Scratch
__device__ float g_y[BLD];
__device__ float g_dt[BLD];
__device__ float g_Bm[BLN];
__device__ float g_Cm[BLN];
__device__ float g_P[CHN];
__device__ float g_He[CHN];
__device__ float g_carry[CHN];
__device__ __nv_bfloat16 g_Xcat0[(size_t)MM * KC];       // [Xh | Xl | Xh]
__device__ __nv_bfloat16 g_Xcat1[(size_t)MM * KC];       // z split
__device__ __nv_bfloat16 g_Wcat[5 * (size_t)NW * KC];    // [hi|hi|lo], transposed, 576-row slots

__device__ __forceinline__ float softplusf(float x) {
    return fmaxf(x, 0.f) + log1pf(__expf(-fabsf(x)));
}

__device__ __forceinline__ uint32_t smem_u32(const void* p) {
    uint32_t a;
    asm("{ .reg .u64 t; cvta.to.shared.u64 t, %1; cvt.u32.u64 %0, t; }" : "=r"(a) : "l"(p));
    return a;
}

// swizzled byte offset inside a 128B-row tile: r = row, c = 16B chunk in [0,8)
__device__ __forceinline__ uint32_t swz(int r, int c) {
    return ((uint32_t)r << 7) + ((uint32_t)(c ^ (r & 7)) << 4);
}

// ---------------------------------------------------------------------------
// bf16 HMMA GEMM, 4-stage cp.async pipeline, warp tile 32x32 (4M x 2N warps).
// C[M=4096, Ncols] = Xcat[M, KC] @ Wcat[Ncols, KC]^T  (TN)
// Tile 128(M) x 64(N), BK=64, 256 thr, 2 CTA/SM.
// EPI 0: bias (N=512)                  grid (8, 32)
// EPI 1: dt softplus + Bm/Cm fused     grid (9, 32)
// EPI 2: bias + bf16-split to xout     grid (8, 32)
// ---------------------------------------------------------------------------
#define BK 64
#define STG 4
#define ABYTES 16384
#define BBYTES 8192
#define STAGE_BYTES (ABYTES + BBYTES)
#define TC_SMEM (STG * STAGE_BYTES)

template<int EPI>
__global__ void __launch_bounds__(256, 2)
tc_gemm(const __nv_bfloat16* __restrict__ A, const __nv_bfloat16* __restrict__ Bw,
        const float* __restrict__ bias, const float* __restrict__ bB,
        const float* __restrict__ bC, float* __restrict__ C,
        __nv_bfloat16* __restrict__ xout)
{
    extern __shared__ char smem[];
    uint32_t sbase = smem_u32(smem);

    int tid = threadIdx.x, wid = tid >> 5, lane = tid & 31;
    int bn = blockIdx.x * 64, bm = blockIdx.y * 128;
    int wm = wid & 3;           // 0..3 -> m offset wm*32
    int wn = wid >> 2;          // 0..1 -> n offset wn*32

    int lrow = ((lane >> 3) & 1) * 8 + (lane & 7);
    int lck = lane >> 4;
    uint32_t aoff[2][4], boff[2][4];
    #pragma unroll
    for (int mt = 0; mt < 2; mt++)
        #pragma unroll
        for (int ks = 0; ks < 4; ks++)
            aoff[mt][ks] = swz(wm * 32 + mt * 16 + lrow, ks * 2 + lck);
    #pragma unroll
    for (int nt = 0; nt < 2; nt++)
        #pragma unroll
        for (int ks = 0; ks < 4; ks++)
            boff[nt][ks] = ABYTES + swz(wn * 32 + nt * 16 + lrow, ks * 2 + lck);

    int ra = tid >> 1, ca0 = (tid & 1) * 4;
    int rb = tid >> 2, cb0 = (tid & 3) * 2;
    const __nv_bfloat16* gA = A + (size_t)(bm + ra) * KC + ca0 * 8;
    const __nv_bfloat16* gB = Bw + (size_t)(bn + rb) * KC + cb0 * 8;
    uint32_t dA[4], dB[2];
    #pragma unroll
    for (int i = 0; i < 4; i++) dA[i] = swz(ra, ca0 + i);
    #pragma unroll
    for (int i = 0; i < 2; i++) dB[i] = ABYTES + swz(rb, cb0 + i);

    float acc[2][4][4];
    #pragma unroll
    for (int i = 0; i < 2; i++)
        #pragma unroll
        for (int j = 0; j < 4; j++)
            #pragma unroll
            for (int q = 0; q < 4; q++) acc[i][j][q] = 0.f;

    const int NKB = KC / BK;    // 24

    #pragma unroll
    for (int s = 0; s < STG - 1; s++) {
        uint32_t st = sbase + s * STAGE_BYTES;
        int ko = s * BK;
        #pragma unroll
        for (int i = 0; i < 4; i++)
            asm volatile("cp.async.cg.shared.global [%0], [%1], 16;" :: "r"(st + dA[i]), "l"(gA + ko + i * 8));
        #pragma unroll
        for (int i = 0; i < 2; i++)
            asm volatile("cp.async.cg.shared.global [%0], [%1], 16;" :: "r"(st + dB[i]), "l"(gB + ko + i * 8));
        asm volatile("cp.async.commit_group;" ::: "memory");
    }

    uint32_t bufA[2][2][4], bufB[2][2][4];

    int sbuf = 0;
    for (int kb = 0; kb < NKB; kb++) {
        asm volatile("cp.async.wait_group %0;" :: "n"(STG - 2) : "memory");
        __syncthreads();

        int knext = kb + STG - 1;
        if (knext < NKB) {
            int sn = knext % STG;
            uint32_t st = sbase + sn * STAGE_BYTES;
            int ko = knext * BK;
            #pragma unroll
            for (int i = 0; i < 4; i++)
                asm volatile("cp.async.cg.shared.global [%0], [%1], 16;" :: "r"(st + dA[i]), "l"(gA + ko + i * 8));
            #pragma unroll
            for (int i = 0; i < 2; i++)
                asm volatile("cp.async.cg.shared.global [%0], [%1], 16;" :: "r"(st + dB[i]), "l"(gB + ko + i * 8));
        }
        asm volatile("cp.async.commit_group;" ::: "memory");

        uint32_t st = sbase + sbuf * STAGE_BYTES;

        // prime ks=0 operands
        #pragma unroll
        for (int mt = 0; mt < 2; mt++)
            asm volatile("ldmatrix.sync.aligned.m8n8.x4.shared.b16 {%0,%1,%2,%3}, [%4];"
                         : "=r"(bufA[0][mt][0]), "=r"(bufA[0][mt][1]),
                           "=r"(bufA[0][mt][2]), "=r"(bufA[0][mt][3])
                         : "r"(st + aoff[mt][0]));
        #pragma unroll
        for (int nt = 0; nt < 2; nt++)
            asm volatile("ldmatrix.sync.aligned.m8n8.x4.shared.b16 {%0,%1,%2,%3}, [%4];"
                         : "=r"(bufB[0][nt][0]), "=r"(bufB[0][nt][1]),
                           "=r"(bufB[0][nt][2]), "=r"(bufB[0][nt][3])
                         : "r"(st + boff[nt][0]));

        #pragma unroll
        for (int ks = 0; ks < 4; ks++) {
            int cb = ks & 1, nb = cb ^ 1;
            if (ks < 3) {
                #pragma unroll
                for (int mt = 0; mt < 2; mt++)
                    asm volatile("ldmatrix.sync.aligned.m8n8.x4.shared.b16 {%0,%1,%2,%3}, [%4];"
                                 : "=r"(bufA[nb][mt][0]), "=r"(bufA[nb][mt][1]),
                                   "=r"(bufA[nb][mt][2]), "=r"(bufA[nb][mt][3])
                                 : "r"(st + aoff[mt][ks + 1]));
                #pragma unroll
                for (int nt = 0; nt < 2; nt++)
                    asm volatile("ldmatrix.sync.aligned.m8n8.x4.shared.b16 {%0,%1,%2,%3}, [%4];"
                                 : "=r"(bufB[nb][nt][0]), "=r"(bufB[nb][nt][1]),
                                   "=r"(bufB[nb][nt][2]), "=r"(bufB[nb][nt][3])
                                 : "r"(st + boff[nt][ks + 1]));
            }
            #pragma unroll
            for (int mt = 0; mt < 2; mt++)
                #pragma unroll
                for (int nt = 0; nt < 2; nt++)
                    #pragma unroll
                    for (int nf = 0; nf < 2; nf++)
                        asm volatile(
                            "mma.sync.aligned.m16n8k16.row.col.f32.bf16.bf16.f32 "
                            "{%0,%1,%2,%3}, {%4,%5,%6,%7}, {%8,%9}, {%0,%1,%2,%3};"
                            : "+f"(acc[mt][nt * 2 + nf][0]), "+f"(acc[mt][nt * 2 + nf][1]),
                              "+f"(acc[mt][nt * 2 + nf][2]), "+f"(acc[mt][nt * 2 + nf][3])
                            : "r"(bufA[cb][mt][0]), "r"(bufA[cb][mt][1]),
                              "r"(bufA[cb][mt][2]), "r"(bufA[cb][mt][3]),
                              "r"(bufB[cb][nt][nf]), "r"(bufB[cb][nt][2 + nf]));
        }
        sbuf++;
        if (sbuf == STG) sbuf = 0;
    }

    // epilogue
    int mbase = bm + wm * 32 + (lane >> 2);
    int nbase = bn + wn * 32 + (lane & 3) * 2;
    #pragma unroll
    for (int mt = 0; mt < 2; mt++) {
        #pragma unroll
        for (int jf = 0; jf < 4; jf++) {
            int col = nbase + (jf >> 1) * 16 + (jf & 1) * 8;
            int m0 = mbase + mt * 16;
            float b0, b1;
            if (EPI == 1 && col >= 512) {
                if (col < 528)      { b0 = bB[col - 512]; b1 = bB[col - 511]; }
                else if (col < 544) { b0 = bC[col - 528]; b1 = bC[col - 527]; }
                else                { b0 = 0.f; b1 = 0.f; }
            } else {
                b0 = bias[col]; b1 = bias[col + 1];
            }
            float v0 = acc[mt][jf][0] + b0, v1 = acc[mt][jf][1] + b1;
            float v2 = acc[mt][jf][2] + b0, v3 = acc[mt][jf][3] + b1;

            if (EPI == 1 && col >= 512) {
                if (col < 528) {
                    int n = col - 512;
                    *(float2*)(g_Bm + (size_t)m0 * NN + n)       = make_float2(v0, v1);
                    *(float2*)(g_Bm + (size_t)(m0 + 8) * NN + n) = make_float2(v2, v3);
                } else if (col < 544) {
                    int n = col - 528;
                    *(float2*)(g_Cm + (size_t)m0 * NN + n)       = make_float2(v0, v1);
                    *(float2*)(g_Cm + (size_t)(m0 + 8) * NN + n) = make_float2(v2, v3);
                }
                continue;
            }
            if (EPI == 1) { v0 = softplusf(v0); v1 = softplusf(v1); v2 = softplusf(v2); v3 = softplusf(v3); }
            *(float2*)(C + (size_t)m0 * DD + col)       = make_float2(v0, v1);
            *(float2*)(C + (size_t)(m0 + 8) * DD + col) = make_float2(v2, v3);
            if (EPI == 2) {
                __nv_bfloat16 h0 = __float2bfloat16_rn(v0), h1 = __float2bfloat16_rn(v1);
                __nv_bfloat16 h2 = __float2bfloat16_rn(v2), h3 = __float2bfloat16_rn(v3);
                __nv_bfloat162 hv0(h0, h1), hv1(h2, h3);
                __nv_bfloat162 lv0(__float2bfloat16_rn(v0 - __bfloat162float(h0)),
                                   __float2bfloat16_rn(v1 - __bfloat162float(h1)));
                __nv_bfloat162 lv1(__float2bfloat16_rn(v2 - __bfloat162float(h2)),
                                   __float2bfloat16_rn(v3 - __bfloat162float(h3)));
                __nv_bfloat16* r0 = xout + (size_t)m0 * KC + col;
                __nv_bfloat16* r1 = xout + (size_t)(m0 + 8) * KC + col;
                *(__nv_bfloat162*)(r0)        = hv0;
                *(__nv_bfloat162*)(r0 + 512)  = lv0;
                *(__nv_bfloat162*)(r0 + 1024) = hv0;
                *(__nv_bfloat162*)(r1)        = hv1;
                *(__nv_bfloat162*)(r1 + 512)  = lv1;
                *(__nv_bfloat162*)(r1 + 1024) = hv1;
            }
        }
    }
}

// ---------------------------------------------------------------------------
// Activation split (x only)
// ---------------------------------------------------------------------------
__global__ void splitx_k(const float4* __restrict__ in)
{
    int i = blockIdx.x * blockDim.x + threadIdx.x;
    int m = i >> 7;
    int k4 = (i & 127) << 2;
    float4 v = in[i];
    __nv_bfloat162 h0(__float2bfloat16_rn(v.x), __float2bfloat16_rn(v.y));
    __nv_bfloat162 h1(__float2bfloat16_rn(v.z), __float2bfloat16_rn(v.w));
    __nv_bfloat162 l0(__float2bfloat16_rn(v.x - __bfloat162float(h0.x)),
                      __float2bfloat16_rn(v.y - __bfloat162float(h0.y)));
    __nv_bfloat162 l1(__float2bfloat16_rn(v.z - __bfloat162float(h1.x)),
                      __float2bfloat16_rn(v.w - __bfloat162float(h1.y)));
    __nv_bfloat16* row = g_Xcat0 + (size_t)m * KC;
    *(__nv_bfloat162*)(row + k4)        = h0;
    *(__nv_bfloat162*)(row + k4 + 2)    = h1;
    *(__nv_bfloat162*)(row + k4 + 512)  = l0;
    *(__nv_bfloat162*)(row + k4 + 514)  = l1;
    *(__nv_bfloat162*)(row + k4 + 1024) = h0;
    *(__nv_bfloat162*)(row + k4 + 1026) = h1;
}

// ---------------------------------------------------------------------------
// Big-weight transpose+split. blockIdx.z = slot.
// ---------------------------------------------------------------------------
__global__ void tsplit_all_k(const float* __restrict__ Wdt, const float* __restrict__ Wlin,
                             const float* __restrict__ Wdec)
{
    __shared__ float t[32][33];
    int slot = blockIdx.z;
    const float* W = (slot == 0) ? Wdt
                   : (slot == 1) ? Wdt + (size_t)DD * DD
                   : (slot == 2) ? Wlin
                   : (slot == 3) ? Wlin + (size_t)DD * DD
                                 : Wdec;
    __nv_bfloat16* out = g_Wcat + (size_t)slot * NW * KC;

    int bk = blockIdx.x * 32, bn = blockIdx.y * 32;
    int tx = threadIdx.x, ty = threadIdx.y;
    #pragma unroll
    for (int i = 0; i < 32; i += 8)
        t[ty + i][tx] = W[(size_t)(bk + ty + i) * DD + bn + tx];
    __syncthreads();
    #pragma unroll
    for (int i = 0; i < 32; i += 8) {
        float v = t[tx][ty + i];
        __nv_bfloat16 h = __float2bfloat16_rn(v);
        __nv_bfloat16 l = __float2bfloat16_rn(v - __bfloat162float(h));
        size_t o = (size_t)(bn + ty + i) * KC + bk + tx;
        out[o]        = h;
        out[o + 512]  = h;
        out[o + 1024] = l;
    }
}

// ---------------------------------------------------------------------------
// WB/WC transpose+split into rows 512..575 of dt slots.
// ---------------------------------------------------------------------------
__global__ void tsplit_bc_k(const float* __restrict__ WB, const float* __restrict__ WC)
{
    int l = blockIdx.y;
    int bk = blockIdx.x * 32;
    int tx = threadIdx.x;
    __nv_bfloat16* out = g_Wcat + (size_t)l * NW * KC + (size_t)512 * KC;

    for (int r = threadIdx.y; r < 64; r += 8) {
        float v = 0.f;
        if (r < 16)      v = WB[(size_t)l * DD * NN + (size_t)(bk + tx) * NN + r];
        else if (r < 32) v = WC[(size_t)l * DD * NN + (size_t)(bk + tx) * NN + (r - 16)];
        __nv_bfloat16 h = __float2bfloat16_rn(v);
        __nv_bfloat16 lo = __float2bfloat16_rn(v - __bfloat162float(h));
        size_t o = (size_t)r * KC + bk + tx;
        out[o]        = h;
        out[o + 512]  = h;
        out[o + 1024] = lo;
    }
}

// ---------------------------------------------------------------------------
// Scan pass 1
// ---------------------------------------------------------------------------
__global__ void scan1_k(const float* __restrict__ yin, const float* __restrict__ A)
{
    __shared__ float sB[LCH * NN];
    int d = blockIdx.x * 128 + threadIdx.x;
    int c = blockIdx.y, b = blockIdx.z;
    int t0 = c * LCH;

    const float4* src = (const float4*)(g_Bm + ((size_t)b * LL + t0) * NN);
    #pragma unroll
    for (int i = threadIdx.x; i < LCH * NN / 4; i += 128)
        ((float4*)sB)[i] = src[i];
    __syncthreads();

    float av[NN], h[NN], p[NN];
    #pragma unroll
    for (int q = 0; q < 4; q++)
        *(float4*)(av + q * 4) = *(const float4*)(A + (size_t)d * NN + q * 4);
    #pragma unroll
    for (int n = 0; n < NN; n++) { h[n] = 0.f; p[n] = 1.f; }

    const float* dtp = g_dt + ((size_t)b * LL + t0) * DD + d;
    const float* yp  = yin  + ((size_t)b * LL + t0) * DD + d;

    for (int t = 0; t < LCH; t++) {
        float dv = dtp[(size_t)t * DD];
        float u  = dv * yp[(size_t)t * DD];
        #pragma unroll
        for (int n = 0; n < NN; n++) {
            float e = __expf(dv * av[n]);
            p[n] *= e;
            h[n] = fmaf(e, h[n], u * sB[t * NN + n]);
        }
    }

    size_t o = (((size_t)b * NCH + c) * DD + d) * NN;
    #pragma unroll
    for (int q = 0; q < 4; q++) {
        *(float4*)(g_P  + o + q * 4) = *(float4*)(p + q * 4);
        *(float4*)(g_He + o + q * 4) = *(float4*)(h + q * 4);
    }
}

// ---------------------------------------------------------------------------
// Scan pass 2 (batched loads)
// ---------------------------------------------------------------------------
__global__ void scan2_k()
{
    int tid = blockIdx.x * blockDim.x + threadIdx.x;
    int b  = tid >> 13;
    int dn = tid & 8191;
    size_t base = (size_t)b * NCH * DD * NN + dn;

    float p[NCH], he[NCH];
    #pragma unroll
    for (int c = 0; c < NCH; c++) {
        p[c]  = g_P [base + (size_t)c * DD * NN];
        he[c] = g_He[base + (size_t)c * DD * NN];
    }
    float hc = 0.f;
    float cr[NCH];
    #pragma unroll
    for (int c = 0; c < NCH; c++) {
        cr[c] = hc;
        hc = fmaf(p[c], hc, he[c]);
    }
    #pragma unroll
    for (int c = 0; c < NCH; c++)
        g_carry[base + (size_t)c * DD * NN] = cr[c];
}

// ---------------------------------------------------------------------------
// Scan pass 3: rescan with carry; write z as bf16 split into Xcat1.
// ---------------------------------------------------------------------------
__global__ void scan3_k(const float* __restrict__ yin, const float* __restrict__ A,
                        const float* __restrict__ Dskip)
{
    __shared__ float sB[LCH * NN];
    __shared__ float sC[LCH * NN];
    int d = blockIdx.x * 128 + threadIdx.x;
    int c = blockIdx.y, b = blockIdx.z;
    int t0 = c * LCH;

    {
        const float4* srcB = (const float4*)(g_Bm + ((size_t)b * LL + t0) * NN);
        const float4* srcC = (const float4*)(g_Cm + ((size_t)b * LL + t0) * NN);
        #pragma unroll
        for (int i = threadIdx.x; i < LCH * NN / 4; i += 128) {
            ((float4*)sB)[i] = srcB[i];
            ((float4*)sC)[i] = srcC[i];
        }
    }
    __syncthreads();

    float av[NN], h[NN];
    #pragma unroll
    for (int q = 0; q < 4; q++)
        *(float4*)(av + q * 4) = *(const float4*)(A + (size_t)d * NN + q * 4);
    size_t co = (((size_t)b * NCH + c) * DD + d) * NN;
    #pragma unroll
    for (int q = 0; q < 4; q++)
        *(float4*)(h + q * 4) = *(const float4*)(g_carry + co + q * 4);

    float ds = Dskip[d];
    const float* dtp = g_dt + ((size_t)b * LL + t0) * DD + d;
    const float* yp  = yin  + ((size_t)b * LL + t0) * DD + d;
    __nv_bfloat16* zb = g_Xcat1 + ((size_t)b * LL + t0) * KC + d;

    for (int t = 0; t < LCH; t++) {
        float dv = dtp[(size_t)t * DD];
        float yv = yp[(size_t)t * DD];
        float u  = dv * yv;
        float acc = 0.f;
        #pragma unroll
        for (int n = 0; n < NN; n++) {
            float e = __expf(dv * av[n]);
            h[n] = fmaf(e, h[n], u * sB[t * NN + n]);
            acc = fmaf(h[n], sC[t * NN + n], acc);
        }
        float z = fmaxf(fmaf(ds, yv, acc), 0.f);
        __nv_bfloat16 hi = __float2bfloat16_rn(z);
        __nv_bfloat16 lo = __float2bfloat16_rn(z - __bfloat162float(hi));
        __nv_bfloat16* zr = zb + (size_t)t * KC;
        zr[0]    = hi;
        zr[512]  = lo;
        zr[1024] = hi;
    }
}

// ---------------------------------------------------------------------------
// Host launcher
// ---------------------------------------------------------------------------
extern "C" void kernel_launch(void* const* d_in, const int* in_sizes, int n_in,
                              void* d_out, int out_size)
{
    const float* x     = (const float*)d_in[0];
    const float* A     = (const float*)d_in[1];
    const float* Dskip = (const float*)d_in[2];
    const float* WB    = (const float*)d_in[3];
    const float* bB    = (const float*)d_in[4];
    const float* WC    = (const float*)d_in[5];
    const float* bC    = (const float*)d_in[6];
    const float* Wdt   = (const float*)d_in[7];
    const float* bdt   = (const float*)d_in[8];
    const float* Wlin  = (const float*)d_in[9];
    const float* blin  = (const float*)d_in[10];
    const float* Wdec  = (const float*)d_in[11];
    const float* bdec  = (const float*)d_in[12];
    float* out = (float*)d_out;

    float *py, *pdt;
    __nv_bfloat16 *px0, *px1, *pwc;
    cudaGetSymbolAddress((void**)&py,  g_y);
    cudaGetSymbolAddress((void**)&pdt, g_dt);
    cudaGetSymbolAddress((void**)&px0, g_Xcat0);
    cudaGetSymbolAddress((void**)&px1, g_Xcat1);
    cudaGetSymbolAddress((void**)&pwc, g_Wcat);

    cudaFuncSetAttribute(tc_gemm<0>, cudaFuncAttributeMaxDynamicSharedMemorySize, TC_SMEM);
    cudaFuncSetAttribute(tc_gemm<1>, cudaFuncAttributeMaxDynamicSharedMemorySize, TC_SMEM);
    cudaFuncSetAttribute(tc_gemm<2>, cudaFuncAttributeMaxDynamicSharedMemorySize, TC_SMEM);

    const size_t WCSZ = (size_t)NW * KC;

    dim3 tgrid(16, 16, 5), tblk(32, 8);
    tsplit_all_k<<<tgrid, tblk>>>(Wdt, Wlin, Wdec);
    tsplit_bc_k<<<dim3(16, 2), tblk>>>(WB, WC);

    dim3 gG1(NW / 64, MM / 128);   // (9, 32) fused dt+BC
    dim3 gG(DD / 64, MM / 128);    // (8, 32)
    dim3 gs(DD / 128, NCH, BB);

    splitx_k<<<(BLD / 4) / 256, 256>>>((const float4*)x);

    const float* cur = x;
    for (int l = 0; l < NLAYER; l++) {
        tc_gemm<1><<<gG1, 256, TC_SMEM>>>(px0, pwc + (size_t)l * WCSZ, bdt + l * DD,
                                          bB + l * NN, bC + l * NN, pdt, nullptr);
        scan1_k<<<gs, 128>>>(cur, A + (size_t)l * DD * NN);
        scan2_k<<<(BB * DD * NN) / 256, 256>>>();
        scan3_k<<<gs, 128>>>(cur, A + (size_t)l * DD * NN, Dskip + l * DD);
        tc_gemm<2><<<gG, 256, TC_SMEM>>>(px1, pwc + (size_t)(2 + l) * WCSZ, blin + l * DD,
                                         nullptr, nullptr, py, px0);
        cur = py;
    }
    tc_gemm<0><<<gG, 256, TC_SMEM>>>(px0, pwc + 4 * WCSZ, bdec, nullptr, nullptr, out, nullptr);
}